// round 14
// baseline (speedup 1.0000x reference)
#include <cuda_runtime.h>
#include <cuda_fp16.h>
#include <math.h>
#include <stdint.h>

#define LSEQ   2048
#define DMODEL 512
#define NLAYER 8
#define DSTATE 16
#define DCONV  4
#define DINNER 1024
#define DTRANK 32
#define VOCAB  4096
#define XDIM   64   // DT_RANK + 2*D_STATE

// ---------------- scratch (static device globals; no allocation) ----------------
__device__ float g_h[LSEQ * DMODEL];
__device__ float g_xz[LSEQ * 2 * DINNER];
__device__ float g_u[LSEQ * DINNER];
__device__ float g_uT[DINNER * LSEQ];
__device__ float g_xpart[4 * LSEQ * XDIM];
__device__ float g_bcT[2 * DSTATE * LSEQ];  // B rows [0..15], C rows [16..31], transposed
__device__ float g_deltaT[DINNER * LSEQ];
__device__ float g_loss[4];                 // [0]=nll sum, [1]=count, [2]=done ticket

// fp16 buffers
__device__ __half g_a16[LSEQ * DINNER];
__device__ __half g_wemb16[VOCAB * DMODEL];
__device__ __half g_win16[NLAYER * 2 * DINNER * DMODEL];
__device__ __half g_wout16[NLAYER * DMODEL * DINNER];

// =============================== PTX helpers ===============================
__device__ __forceinline__ uint32_t smem_to_u32(const void* p) {
    uint32_t a;
    asm("{ .reg .u64 t; cvta.to.shared.u64 t, %1; cvt.u32.u64 %0, t; }"
        : "=r"(a) : "l"(p));
    return a;
}

#define CP_ASYNC_16(dst, src) \
    asm volatile("cp.async.cg.shared.global [%0], [%1], 16;" \
        :: "r"(dst), "l"(src) : "memory")
#define CP_ASYNC_COMMIT() asm volatile("cp.async.commit_group;" ::: "memory")
#define CP_ASYNC_WAIT0()  asm volatile("cp.async.wait_group 0;" ::: "memory")

__device__ __forceinline__ void ldmatrix_x4(uint32_t* r, uint32_t addr) {
    asm volatile("ldmatrix.sync.aligned.m8n8.x4.shared.b16 {%0,%1,%2,%3}, [%4];"
        : "=r"(r[0]), "=r"(r[1]), "=r"(r[2]), "=r"(r[3]) : "r"(addr));
}

__device__ __forceinline__ void mma16816(float* c, const uint32_t* a, const uint32_t* b) {
    asm volatile(
        "mma.sync.aligned.m16n8k16.row.col.f32.f16.f16.f32 "
        "{%0,%1,%2,%3}, {%4,%5,%6,%7}, {%8,%9}, {%0,%1,%2,%3};"
        : "+f"(c[0]), "+f"(c[1]), "+f"(c[2]), "+f"(c[3])
        : "r"(a[0]), "r"(a[1]), "r"(a[2]), "r"(a[3]), "r"(b[0]), "r"(b[1]));
}

// ======================= fp16 HMMA GEMM =======================
// C[M,N] = A[M,K] * B[N,K]^T, fp16 in, fp32 acc.
// CTA tile 128xBN, K chunks of CHUNK, cp.async double buffer.
// 256 threads = 8 warps; BN=128: 2m x 4n (warp tile 64x32); BN=64: 4m x 2n (32x32).
// smem row stride = CHUNK+8 fp16 -> ldmatrix conflict-free.
// kk-loop fragments are manually double-buffered (load kk+1 while kk's mma issue).

template <int ROWS, int CHUNK>
__device__ __forceinline__ void hmma_fill(
    uint32_t sdst, const __half* __restrict__ g, int ld, int row0, int k0, int tid) {
    constexpr int STRIDE = CHUNK + 8;
    constexpr int SEGS = CHUNK / 8;
    #pragma unroll
    for (int r = 0; r < ROWS * SEGS / 256; r++) {
        int idx = r * 256 + tid;
        int row = idx / SEGS, seg = idx % SEGS;
        uint32_t so = sdst + (uint32_t)(row * STRIDE + seg * 8) * 2;
        const void* gp = g + (size_t)(row0 + row) * ld + k0 + seg * 8;
        CP_ASYNC_16(so, gp);
    }
}

// EPI: 0 = store, 2 = += resid
template <int EPI, int BN, int CHUNK>
__global__ void __launch_bounds__(256) gemm_hmma_kernel(
    int K,
    const __half* __restrict__ A, int lda,
    const __half* __restrict__ B, int ldb,
    float* __restrict__ C, int ldc,
    const float* __restrict__ resid) {
    extern __shared__ __half smem[];
    const uint32_t sbu = smem_to_u32(smem);
    const int tid = threadIdx.x;
    const int wid = tid >> 5, lane = tid & 31;
    const int bm0 = blockIdx.y * 128, bn0 = blockIdx.x * BN;

    constexpr int STRIDE = CHUNK + 8;
    constexpr int A_ELE = 128 * STRIDE;
    constexpr int B_ELE = BN * STRIDE;
    constexpr int BUF_ELE = A_ELE + B_ELE;
    constexpr int MT = (BN == 128) ? 4 : 2;
    constexpr int KK = CHUNK / 16;

    const int wm = (BN == 128) ? (wid >> 2) * 64 : (wid >> 1) * 32;
    const int wn = (BN == 128) ? (wid & 3) * 32 : (wid & 1) * 32;

    float acc[MT][4][4];
    #pragma unroll
    for (int i = 0; i < MT; i++)
        #pragma unroll
        for (int j = 0; j < 4; j++)
            #pragma unroll
            for (int q = 0; q < 4; q++) acc[i][j][q] = 0.f;

    const int NC = K / CHUNK;

    hmma_fill<128, CHUNK>(sbu,            A, lda, bm0, 0, tid);
    hmma_fill<BN, CHUNK>(sbu + A_ELE * 2, B, ldb, bn0, 0, tid);
    CP_ASYNC_COMMIT();

    const int a_row = ((lane >> 3) & 1) * 8 + (lane & 7);
    const int a_col = ((lane >> 4) & 1) * 8;
    const int b_row = ((lane >> 4) & 1) * 8 + (lane & 7);
    const int b_col = ((lane >> 3) & 1) * 8;

    uint32_t ah[2][MT][4], bh[2][4][2];

    auto load_frags = [&](uint32_t sA, uint32_t sB, int kk, int set) {
        const int kc = kk * 16;
        #pragma unroll
        for (int mt = 0; mt < MT; mt++) {
            uint32_t off = (uint32_t)((wm + mt * 16 + a_row) * STRIDE + kc + a_col) * 2;
            ldmatrix_x4(ah[set][mt], sA + off);
        }
        #pragma unroll
        for (int nt2 = 0; nt2 < 2; nt2++) {
            uint32_t off = (uint32_t)((wn + nt2 * 16 + b_row) * STRIDE + kc + b_col) * 2;
            uint32_t r[4];
            ldmatrix_x4(r, sB + off);
            bh[set][nt2 * 2][0] = r[0]; bh[set][nt2 * 2][1] = r[1];
            bh[set][nt2 * 2 + 1][0] = r[2]; bh[set][nt2 * 2 + 1][1] = r[3];
        }
    };

    for (int ck = 0; ck < NC; ck++) {
        const int b = ck & 1;
        CP_ASYNC_WAIT0();
        __syncthreads();
        if (ck + 1 < NC) {
            uint32_t nb = sbu + (uint32_t)((b ^ 1) * BUF_ELE) * 2;
            const int k0 = (ck + 1) * CHUNK;
            hmma_fill<128, CHUNK>(nb,            A, lda, bm0, k0, tid);
            hmma_fill<BN, CHUNK>(nb + A_ELE * 2, B, ldb, bn0, k0, tid);
            CP_ASYNC_COMMIT();
        }

        const uint32_t sA = sbu + (uint32_t)(b * BUF_ELE) * 2;
        const uint32_t sB = sA + (uint32_t)A_ELE * 2;

        load_frags(sA, sB, 0, 0);
        #pragma unroll
        for (int kk = 0; kk < KK; kk++) {
            const int cur = kk & 1;
            if (kk + 1 < KK) load_frags(sA, sB, kk + 1, cur ^ 1);
            #pragma unroll
            for (int mt = 0; mt < MT; mt++)
                #pragma unroll
                for (int nt = 0; nt < 4; nt++)
                    mma16816(acc[mt][nt], ah[cur][mt], bh[cur][nt]);
        }
        __syncthreads();
    }

    const int er = lane >> 2, ec = (lane & 3) * 2;
    #pragma unroll
    for (int mt = 0; mt < MT; mt++) {
        #pragma unroll
        for (int nt = 0; nt < 4; nt++) {
            int row = bm0 + wm + mt * 16 + er;
            int col = bn0 + wn + nt * 8 + ec;
            float2 v0 = make_float2(acc[mt][nt][0], acc[mt][nt][1]);
            float2 v1 = make_float2(acc[mt][nt][2], acc[mt][nt][3]);
            if (EPI == 2) {
                const float2 r0 = *reinterpret_cast<const float2*>(
                    resid + (size_t)row * ldc + col);
                const float2 r1 = *reinterpret_cast<const float2*>(
                    resid + (size_t)(row + 8) * ldc + col);
                v0.x += r0.x; v0.y += r0.y;
                v1.x += r1.x; v1.y += r1.y;
            }
            *reinterpret_cast<float2*>(C + (size_t)row * ldc + col) = v0;
            *reinterpret_cast<float2*>(C + (size_t)(row + 8) * ldc + col) = v1;
        }
    }
}

#define HT_SMEM(BN, CHUNK) (2 * (128 + (BN)) * ((CHUNK) + 8) * 2)
#define HT_SMEM_128_64 HT_SMEM(128, 64)     // 73,728 B
#define HT_SMEM_64_128 HT_SMEM(64, 128)     // 104,448 B

// ---------------- fused fp32 -> fp16 conversion of all weights ----------------
#define CVT_N1 (VOCAB * DMODEL)
#define CVT_N2 (NLAYER * 2 * DINNER * DMODEL)
#define CVT_N3 (NLAYER * DMODEL * DINNER)
__global__ void cvt_all_kernel(const float* __restrict__ emb,
                               const float* __restrict__ inw,
                               const float* __restrict__ ow,
                               __half* __restrict__ we16,
                               __half* __restrict__ wi16,
                               __half* __restrict__ wo16) {
    int i = (blockIdx.x * blockDim.x + threadIdx.x) * 4;
    const float* src;
    __half* dst;
    if (i < CVT_N1) {
        src = emb + i; dst = we16 + i;
    } else if (i < CVT_N1 + CVT_N2) {
        src = inw + (i - CVT_N1); dst = wi16 + (i - CVT_N1);
    } else if (i < CVT_N1 + CVT_N2 + CVT_N3) {
        src = ow + (i - CVT_N1 - CVT_N2); dst = wo16 + (i - CVT_N1 - CVT_N2);
    } else {
        return;
    }
    float4 v = *reinterpret_cast<const float4*>(src);
    *reinterpret_cast<__half2*>(dst)     = __floats2half2_rn(v.x, v.y);
    *reinterpret_cast<__half2*>(dst + 2) = __floats2half2_rn(v.z, v.w);
}

// ---------------- block reductions (loss only) ----------------
__device__ __forceinline__ float blockReduceSum(float v) {
    __shared__ float sh[9];
    int lane = threadIdx.x & 31, w = threadIdx.x >> 5;
    #pragma unroll
    for (int o = 16; o; o >>= 1) v += __shfl_xor_sync(0xffffffffu, v, o);
    if (lane == 0) sh[w] = v;
    __syncthreads();
    if (threadIdx.x == 0) {
        float s = 0.f;
        int nw = (blockDim.x + 31) >> 5;
        for (int i = 0; i < nw; i++) s += sh[i];
        sh[8] = s;
    }
    __syncthreads();
    float r = sh[8];
    __syncthreads();
    return r;
}

__device__ __forceinline__ float blockReduceMax(float v) {
    __shared__ float sh[9];
    int lane = threadIdx.x & 31, w = threadIdx.x >> 5;
    #pragma unroll
    for (int o = 16; o; o >>= 1) v = fmaxf(v, __shfl_xor_sync(0xffffffffu, v, o));
    if (lane == 0) sh[w] = v;
    __syncthreads();
    if (threadIdx.x == 0) {
        float s = -1e30f;
        int nw = (blockDim.x + 31) >> 5;
        for (int i = 0; i < nw; i++) s = fmaxf(s, sh[i]);
        sh[8] = s;
    }
    __syncthreads();
    float r = sh[8];
    __syncthreads();
    return r;
}

// ---------------- embedding ----------------
__global__ void embed_kernel(const int* __restrict__ ids,
                             const float* __restrict__ emb,
                             const float* __restrict__ pos) {
    int i = blockIdx.x * blockDim.x + threadIdx.x;
    if (i >= LSEQ * DMODEL) return;
    int t = i / DMODEL;
    int d = i - t * DMODEL;
    g_h[i] = emb[(size_t)ids[t] * DMODEL + d] + pos[i];
}

// ---------------- rmsnorm -> fp16, warp per token ----------------
__global__ void rmsnorm_kernel(const float* __restrict__ src,
                               const float* __restrict__ w,
                               __half* __restrict__ dst) {
    int warp = threadIdx.x >> 5, lane = threadIdx.x & 31;
    int t = blockIdx.x * 8 + warp;
    const float* r = src + (size_t)t * DMODEL;
    float4 v[4];
    float ss = 0.f;
    #pragma unroll
    for (int q = 0; q < 4; q++) {
        v[q] = *reinterpret_cast<const float4*>(r + (q * 32 + lane) * 4);
        ss += v[q].x * v[q].x + v[q].y * v[q].y + v[q].z * v[q].z + v[q].w * v[q].w;
    }
    #pragma unroll
    for (int o = 16; o; o >>= 1) ss += __shfl_xor_sync(0xffffffffu, ss, o);
    float sc = rsqrtf(ss * (1.0f / DMODEL) + 1e-6f);
    __half* dp = dst + (size_t)t * DMODEL;
    #pragma unroll
    for (int q = 0; q < 4; q++) {
        int idx = (q * 32 + lane) * 4;
        float4 w4 = *reinterpret_cast<const float4*>(w + idx);
        __half2 h0 = __floats2half2_rn(v[q].x * sc * w4.x, v[q].y * sc * w4.y);
        __half2 h1 = __floats2half2_rn(v[q].z * sc * w4.z, v[q].w * sc * w4.w);
        *reinterpret_cast<__half2*>(dp + idx)     = h0;
        *reinterpret_cast<__half2*>(dp + idx + 2) = h1;
    }
}

// =================================================================================
// fp32 GEMM 64x64x16 (small xproj/dt), double-buffered, 256 threads, 4x4/thread
// split-K via blockIdx.z.
// EPI: 0 = plain store, 1 = softplus(v+bias[col]) stored TRANSPOSED (C[col][row]);
//      EPI==1 blocks with blockIdx.x==0 ALSO reduce the bc split-K partials into
//      g_bcT for their 64-row slice (folds the old reduce4 kernel in).
// SUMA: A elements are the sum of 4 split-K partials at stride LSEQ*XDIM
// =================================================================================
template <int EPI, int SUMA>
__global__ void __launch_bounds__(256) gemm64_kernel(
    int Kloc,
    const float* __restrict__ A, int lda,
    const float* __restrict__ B, int ldb,
    float* __restrict__ C, int ldc, int partStride,
    const float* __restrict__ bias) {
    __shared__ float As[2][16][68];
    __shared__ float Bs[2][16][68];
    const int tid = threadIdx.x;
    const int bm0 = blockIdx.y * 64, bn0 = blockIdx.x * 64;
    const int kbase = blockIdx.z * Kloc;
    C += (size_t)blockIdx.z * partStride;
    const int PS = LSEQ * XDIM;

    // folded reduce4: bcT slice for rows [bm0, bm0+64)
    if (EPI == 1 && blockIdx.x == 0) {
        #pragma unroll
        for (int i = 0; i < 8; i++) {
            int idx = i * 256 + tid;            // 0..2047
            int s2 = idx >> 6, tl = idx & 63;
            int t = bm0 + tl;
            int b = t * XDIM + DTRANK + s2;
            g_bcT[(size_t)s2 * LSEQ + t] =
                g_xpart[b] + g_xpart[b + PS] + g_xpart[b + 2 * PS] + g_xpart[b + 3 * PS];
        }
    }

    const int lrow = tid >> 2;
    const int kq0  = (tid & 3) << 2;
    const float* Ap = A + (size_t)(bm0 + lrow) * lda + kbase + kq0;
    const float* Bp = B + (size_t)(bn0 + lrow) * ldb + kbase + kq0;

    const int ty = tid >> 4, tx = tid & 15;

    float acc[4][4];
    #pragma unroll
    for (int i = 0; i < 4; i++)
        #pragma unroll
        for (int j = 0; j < 4; j++) acc[i][j] = 0.f;

    auto loadA = [&](int off) -> float4 {
        float4 a = *reinterpret_cast<const float4*>(Ap + off);
        if (SUMA) {
            float4 p1 = *reinterpret_cast<const float4*>(Ap + off + PS);
            float4 p2 = *reinterpret_cast<const float4*>(Ap + off + 2 * PS);
            float4 p3 = *reinterpret_cast<const float4*>(Ap + off + 3 * PS);
            a.x = a.x + p1.x + p2.x + p3.x;
            a.y = a.y + p1.y + p2.y + p3.y;
            a.z = a.z + p1.z + p2.z + p3.z;
            a.w = a.w + p1.w + p2.w + p3.w;
        }
        return a;
    };

    float4 av = loadA(0);
    float4 bv = *reinterpret_cast<const float4*>(Bp);
    As[0][kq0 + 0][lrow] = av.x; As[0][kq0 + 1][lrow] = av.y;
    As[0][kq0 + 2][lrow] = av.z; As[0][kq0 + 3][lrow] = av.w;
    Bs[0][kq0 + 0][lrow] = bv.x; Bs[0][kq0 + 1][lrow] = bv.y;
    Bs[0][kq0 + 2][lrow] = bv.z; Bs[0][kq0 + 3][lrow] = bv.w;
    __syncthreads();

    const int KT = Kloc >> 4;
    for (int kt = 0; kt < KT; kt++) {
        const int cur = kt & 1, nxt = cur ^ 1;
        if (kt + 1 < KT) {
            int off = (kt + 1) << 4;
            av = loadA(off);
            bv = *reinterpret_cast<const float4*>(Bp + off);
        }
        #pragma unroll
        for (int kk = 0; kk < 16; kk++) {
            float4 a4 = *reinterpret_cast<const float4*>(&As[cur][kk][ty * 4]);
            float4 b4 = *reinterpret_cast<const float4*>(&Bs[cur][kk][tx * 4]);
            float a[4] = {a4.x, a4.y, a4.z, a4.w};
            float b[4] = {b4.x, b4.y, b4.z, b4.w};
            #pragma unroll
            for (int i = 0; i < 4; i++)
                #pragma unroll
                for (int j = 0; j < 4; j++)
                    acc[i][j] = fmaf(a[i], b[j], acc[i][j]);
        }
        if (kt + 1 < KT) {
            As[nxt][kq0 + 0][lrow] = av.x; As[nxt][kq0 + 1][lrow] = av.y;
            As[nxt][kq0 + 2][lrow] = av.z; As[nxt][kq0 + 3][lrow] = av.w;
            Bs[nxt][kq0 + 0][lrow] = bv.x; Bs[nxt][kq0 + 1][lrow] = bv.y;
            Bs[nxt][kq0 + 2][lrow] = bv.z; Bs[nxt][kq0 + 3][lrow] = bv.w;
            __syncthreads();
        }
    }

    if (EPI == 1) {
        float4 bias4 = *reinterpret_cast<const float4*>(&bias[bn0 + tx * 4]);
        float bb[4] = {bias4.x, bias4.y, bias4.z, bias4.w};
        #pragma unroll
        for (int i = 0; i < 4; i++)
            #pragma unroll
            for (int j = 0; j < 4; j++) {
                float v = acc[i][j] + bb[j];
                acc[i][j] = (v > 20.f) ? v : log1pf(expf(v));
            }
        int row0 = bm0 + ty * 4;
        #pragma unroll
        for (int j = 0; j < 4; j++) {
            int col = bn0 + tx * 4 + j;
            float4 v = make_float4(acc[0][j], acc[1][j], acc[2][j], acc[3][j]);
            *reinterpret_cast<float4*>(C + (size_t)col * ldc + row0) = v;
        }
    } else {
        #pragma unroll
        for (int i = 0; i < 4; i++) {
            int row = bm0 + ty * 4 + i;
            float* cp = C + (size_t)row * ldc + bn0 + tx * 4;
            *reinterpret_cast<float4*>(cp) =
                make_float4(acc[i][0], acc[i][1], acc[i][2], acc[i][3]);
        }
    }
}

// ---------------- depthwise causal conv (width 4) + bias + silu ----------------
__global__ void conv_silu_kernel(const float* __restrict__ cw,
                                 const float* __restrict__ cb) {
    __shared__ float su[64][33];
    const int c0 = blockIdx.x * 64;
    const int t0 = blockIdx.y * 32;
    const int tid = threadIdx.x;
    #pragma unroll
    for (int it = 0; it < 8; it++) {
        int idx = it * 256 + tid;
        int cl = idx & 63, tl = idx >> 6;
        int c = c0 + cl, t = t0 + tl;
        float v = cb[c];
        #pragma unroll
        for (int k = 0; k < DCONV; k++) {
            int tt = t - (DCONV - 1) + k;
            if (tt >= 0)
                v = fmaf(g_xz[(size_t)tt * (2 * DINNER) + c], cw[c * DCONV + k], v);
        }
        float s = v / (1.f + expf(-v));
        g_u[(size_t)t * DINNER + c] = s;
        su[cl][tl] = s;
    }
    __syncthreads();
    #pragma unroll
    for (int it = 0; it < 8; it++) {
        int cl = it * 8 + (tid >> 5);
        int tl = tid & 31;
        g_uT[(size_t)(c0 + cl) * LSEQ + (t0 + tl)] = su[cl][tl];
    }
}

// ---------------- selective scan (fused y-combine, emits fp16) ----------------
__global__ void scan_kernel(const float* __restrict__ deltaT,
                            const float* __restrict__ uT,
                            const float* __restrict__ bcT,
                            const float* __restrict__ A_log,
                            const float* __restrict__ xz,
                            const float* __restrict__ Dp,
                            __half* __restrict__ yout) {
    int warp = threadIdx.x >> 5;
    int lane = threadIdx.x & 31;
    int half = lane >> 4;
    int s    = lane & 15;
    int ch   = blockIdx.x * 8 + warp * 2 + half;

    float A2 = -__expf(A_log[ch * DSTATE + s]) * 1.44269504088896f;
    float dpv = Dp[ch];
    float h = 0.f;
    const float* dT  = deltaT + (size_t)ch * LSEQ;
    const float* uTp = uT + (size_t)ch * LSEQ;
    const float* bT  = bcT + (size_t)s * LSEQ;
    const float* cT  = bcT + (size_t)(DSTATE + s) * LSEQ;

    for (int t0 = 0; t0 < LSEQ; t0 += 16) {
        float dv[16], uv[16], bv[16], cv[16];
        #pragma unroll
        for (int q = 0; q < 4; q++) {
            float4 d4 = *reinterpret_cast<const float4*>(dT + t0 + q * 4);
            float4 u4 = *reinterpret_cast<const float4*>(uTp + t0 + q * 4);
            float4 b4 = *reinterpret_cast<const float4*>(bT + t0 + q * 4);
            float4 c4 = *reinterpret_cast<const float4*>(cT + t0 + q * 4);
            dv[q*4+0]=d4.x; dv[q*4+1]=d4.y; dv[q*4+2]=d4.z; dv[q*4+3]=d4.w;
            uv[q*4+0]=u4.x; uv[q*4+1]=u4.y; uv[q*4+2]=u4.z; uv[q*4+3]=u4.w;
            bv[q*4+0]=b4.x; bv[q*4+1]=b4.y; bv[q*4+2]=b4.z; bv[q*4+3]=b4.w;
            cv[q*4+0]=c4.x; cv[q*4+1]=c4.y; cv[q*4+2]=c4.z; cv[q*4+3]=c4.w;
        }
        float p[16];
        #pragma unroll
        for (int j = 0; j < 16; j++) {
            float dA  = exp2f(dv[j] * A2);
            float dbu = dv[j] * uv[j] * bv[j];
            h = fmaf(dA, h, dbu);
            p[j] = h * cv[j];
        }
        float out = 0.f, uo = 0.f;
        #pragma unroll
        for (int j = 0; j < 16; j++) {
            float v = p[j];
            v += __shfl_xor_sync(0xffffffffu, v, 1);
            v += __shfl_xor_sync(0xffffffffu, v, 2);
            v += __shfl_xor_sync(0xffffffffu, v, 4);
            v += __shfl_xor_sync(0xffffffffu, v, 8);
            if (s == j) { out = v; uo = uv[j]; }
        }
        int t = t0 + s;
        float zz = xz[(size_t)t * (2 * DINNER) + DINNER + ch];
        float sz = zz / (1.f + expf(-zz));
        yout[(size_t)t * DINNER + ch] = __float2half((out + uo * dpv) * sz);
    }
}

// ---------------- cross-entropy loss (fused final divide via ticket) ----------------
__global__ void loss_kernel(const int* __restrict__ labels,
                            const float* __restrict__ logits,
                            float* __restrict__ out, int idx) {
    int t = blockIdx.x;
    const float* row = logits + (size_t)t * VOCAB;
    float mx = -1e30f;
    for (int j = threadIdx.x; j < VOCAB; j += 256) mx = fmaxf(mx, row[j]);
    mx = blockReduceMax(mx);
    float sum = 0.f;
    for (int j = threadIdx.x; j < VOCAB; j += 256) sum += expf(row[j] - mx);
    sum = blockReduceSum(sum);
    if (threadIdx.x == 0) {
        int tgt = labels[t + 1];
        if (tgt != -100) {
            float lp = row[tgt] - mx - logf(sum);
            atomicAdd(&g_loss[0], -lp);
            atomicAdd(&g_loss[1], 1.f);
        }
        __threadfence();
        int ticket = atomicAdd(reinterpret_cast<int*>(&g_loss[2]), 1);
        if (ticket == (int)gridDim.x - 1) {
            out[idx] = g_loss[0] / fmaxf(g_loss[1], 1.f);
        }
    }
}

// ---------------- driver ----------------
extern "C" void kernel_launch(void* const* d_in, const int* in_sizes, int n_in,
                              void* d_out, int out_size) {
    const int*   ids    = (const int*)  d_in[0];
    const int*   labels = (const int*)  d_in[1];
    const float* emb    = (const float*)d_in[2];
    const float* pos    = (const float*)d_in[3];
    const float* fnw    = (const float*)d_in[4];
    const float* nw     = (const float*)d_in[5];
    const float* inw    = (const float*)d_in[6];
    const float* cw     = (const float*)d_in[7];
    const float* cb     = (const float*)d_in[8];
    const float* xw     = (const float*)d_in[9];
    const float* dw     = (const float*)d_in[10];
    const float* db     = (const float*)d_in[11];
    const float* alog   = (const float*)d_in[12];
    const float* dp     = (const float*)d_in[13];
    const float* ow     = (const float*)d_in[14];
    float* out = (float*)d_out;

    float *ph, *pxz, *pu, *puT, *pxpart, *pbcT, *pdT, *ploss;
    __half *pa16, *pwe16, *pwi16, *pwo16;
    cudaGetSymbolAddress((void**)&ph,     g_h);
    cudaGetSymbolAddress((void**)&pxz,    g_xz);
    cudaGetSymbolAddress((void**)&pu,     g_u);
    cudaGetSymbolAddress((void**)&puT,    g_uT);
    cudaGetSymbolAddress((void**)&pxpart, g_xpart);
    cudaGetSymbolAddress((void**)&pbcT,   g_bcT);
    cudaGetSymbolAddress((void**)&pdT,    g_deltaT);
    cudaGetSymbolAddress((void**)&ploss,  g_loss);
    cudaGetSymbolAddress((void**)&pa16,   g_a16);
    cudaGetSymbolAddress((void**)&pwe16,  g_wemb16);
    cudaGetSymbolAddress((void**)&pwi16,  g_win16);
    cudaGetSymbolAddress((void**)&pwo16,  g_wout16);

    cudaFuncSetAttribute((const void*)gemm_hmma_kernel<0, 128, 64>,
        cudaFuncAttributeMaxDynamicSharedMemorySize, HT_SMEM_128_64);
    cudaFuncSetAttribute((const void*)gemm_hmma_kernel<2, 64, 128>,
        cudaFuncAttributeMaxDynamicSharedMemorySize, HT_SMEM_64_128);

    embed_kernel<<<(LSEQ * DMODEL + 255) / 256, 256>>>(ids, emb, pos);
    {
        int total = CVT_N1 + CVT_N2 + CVT_N3;
        cvt_all_kernel<<<(total / 4 + 255) / 256, 256>>>(
            emb, inw, ow, pwe16, pwi16, pwo16);
    }

    for (int l = 0; l < NLAYER; l++) {
        const float* nw_l  = nw   + (size_t)l * DMODEL;
        const float* cw_l  = cw   + (size_t)l * DINNER * DCONV;
        const float* cb_l  = cb   + (size_t)l * DINNER;
        const float* xw_l  = xw   + (size_t)l * XDIM * DINNER;
        const float* dw_l  = dw   + (size_t)l * DINNER * DTRANK;
        const float* db_l  = db   + (size_t)l * DINNER;
        const float* al_l  = alog + (size_t)l * DINNER * DSTATE;
        const float* dp_l  = dp   + (size_t)l * DINNER;
        const __half* wi_l = pwi16 + (size_t)l * 2 * DINNER * DMODEL;
        const __half* wo_l = pwo16 + (size_t)l * DMODEL * DINNER;

        // x = rmsnorm(h) -> fp16 (warp per token)
        rmsnorm_kernel<<<LSEQ / 8, 256>>>(ph, nw_l, pa16);
        // xz = x @ in_w^T  [2048 x 2048], K=512 (HMMA, frag-pipelined)
        gemm_hmma_kernel<0, 128, 64>
            <<<dim3(2 * DINNER / 128, LSEQ / 128), 256, HT_SMEM_128_64>>>(
            DMODEL, pa16, DMODEL, wi_l, DMODEL, pxz, 2 * DINNER, nullptr);
        // u = silu(causal depthwise conv(xi) + b)  (u and u_T, both coalesced)
        conv_silu_kernel<<<dim3(DINNER / 64, LSEQ / 32), 256>>>(cw_l, cb_l);
        // xdbl partials = u @ xproj_w^T  [2048 x 64], K=1024, split-K x4 (fp32)
        gemm64_kernel<0, 0><<<dim3(1, LSEQ / 64, 4), 256>>>(
            DINNER / 4, pu, DINNER, xw_l, DINNER, pxpart, XDIM, LSEQ * XDIM, nullptr);
        // delta_T = softplus((sum dt partials) @ dt_w^T + dt_b)^T; also reduces bcT
        gemm64_kernel<1, 1><<<dim3(DINNER / 64, LSEQ / 64), 256>>>(
            DTRANK, pxpart, XDIM, dw_l, DTRANK, pdT, LSEQ, 0, db_l);
        // selective scan + fused (y + u*Dp)*silu(z) -> fp16
        scan_kernel<<<DINNER / 8, 128>>>(pdT, puT, pbcT, al_l, pxz, dp_l, pa16);
        // h = h + yf @ out_w^T  [2048 x 512], K=1024 (HMMA, frag-pipelined)
        gemm_hmma_kernel<2, 64, 128>
            <<<dim3(DMODEL / 64, LSEQ / 128), 256, HT_SMEM_64_128>>>(
            DINNER, pa16, DINNER, wo_l, DINNER, ph, DMODEL, ph);
    }

    // final norm + logits (HMMA)
    rmsnorm_kernel<<<LSEQ / 8, 256>>>(ph, fnw, pa16);
    gemm_hmma_kernel<0, 128, 64>
        <<<dim3(VOCAB / 128, LSEQ / 128), 256, HT_SMEM_128_64>>>(
        DMODEL, pa16, DMODEL, pwe16, DMODEL, out, VOCAB, nullptr);

    // loss (init via memset node; final divide fused via last-block ticket)
    cudaMemsetAsync(ploss, 0, 4 * sizeof(float));
    loss_kernel<<<LSEQ - 1, 256>>>(labels, out, out, out_size - 1);
}

// round 15
// speedup vs baseline: 1.0049x; 1.0049x over previous
#include <cuda_runtime.h>
#include <cuda_fp16.h>
#include <math.h>
#include <stdint.h>

#define LSEQ   2048
#define DMODEL 512
#define NLAYER 8
#define DSTATE 16
#define DCONV  4
#define DINNER 1024
#define DTRANK 32
#define VOCAB  4096
#define XDIM   64   // DT_RANK + 2*D_STATE

// ---------------- scratch (static device globals; no allocation) ----------------
__device__ float g_h[LSEQ * DMODEL];
__device__ float g_xz[LSEQ * 2 * DINNER];
__device__ float g_u[LSEQ * DINNER];
__device__ float g_uT[DINNER * LSEQ];
__device__ float g_xpart[4 * LSEQ * XDIM];
__device__ float g_bcT[2 * DSTATE * LSEQ];  // B rows [0..15], C rows [16..31], transposed
__device__ float g_deltaT[DINNER * LSEQ];
__device__ float g_loss[4];                 // [0]=nll sum, [1]=count, [2]=done ticket

// fp16 buffers
__device__ __half g_a16[LSEQ * DINNER];
__device__ __half g_wemb16[VOCAB * DMODEL];
__device__ __half g_win16[NLAYER * 2 * DINNER * DMODEL];
__device__ __half g_wout16[NLAYER * DMODEL * DINNER];

// =============================== PTX helpers ===============================
__device__ __forceinline__ uint32_t smem_to_u32(const void* p) {
    uint32_t a;
    asm("{ .reg .u64 t; cvta.to.shared.u64 t, %1; cvt.u32.u64 %0, t; }"
        : "=r"(a) : "l"(p));
    return a;
}

#define CP_ASYNC_16(dst, src) \
    asm volatile("cp.async.cg.shared.global [%0], [%1], 16;" \
        :: "r"(dst), "l"(src) : "memory")
#define CP_ASYNC_COMMIT() asm volatile("cp.async.commit_group;" ::: "memory")
#define CP_ASYNC_WAIT0()  asm volatile("cp.async.wait_group 0;" ::: "memory")

__device__ __forceinline__ void ldmatrix_x4(uint32_t* r, uint32_t addr) {
    asm volatile("ldmatrix.sync.aligned.m8n8.x4.shared.b16 {%0,%1,%2,%3}, [%4];"
        : "=r"(r[0]), "=r"(r[1]), "=r"(r[2]), "=r"(r[3]) : "r"(addr));
}

__device__ __forceinline__ void mma16816(float* c, const uint32_t* a, const uint32_t* b) {
    asm volatile(
        "mma.sync.aligned.m16n8k16.row.col.f32.f16.f16.f32 "
        "{%0,%1,%2,%3}, {%4,%5,%6,%7}, {%8,%9}, {%0,%1,%2,%3};"
        : "+f"(c[0]), "+f"(c[1]), "+f"(c[2]), "+f"(c[3])
        : "r"(a[0]), "r"(a[1]), "r"(a[2]), "r"(a[3]), "r"(b[0]), "r"(b[1]));
}

// ======================= fp16 HMMA GEMM (r11 config — best known) =======================
// C[M,N] = A[M,K] * B[N,K]^T, fp16 in, fp32 acc.
// CTA tile 128xBN, K chunks of CHUNK, cp.async double buffer, OCC CTAs/SM.
// 256 threads = 8 warps; BN=128: 2m x 4n (warp tile 64x32); BN=64: 4m x 2n (32x32).
// smem row stride = CHUNK+8 fp16 -> ldmatrix conflict-free for CHUNK 64/128.

template <int ROWS, int CHUNK>
__device__ __forceinline__ void hmma_fill(
    uint32_t sdst, const __half* __restrict__ g, int ld, int row0, int k0, int tid) {
    constexpr int STRIDE = CHUNK + 8;
    constexpr int SEGS = CHUNK / 8;
    #pragma unroll
    for (int r = 0; r < ROWS * SEGS / 256; r++) {
        int idx = r * 256 + tid;
        int row = idx / SEGS, seg = idx % SEGS;
        uint32_t so = sdst + (uint32_t)(row * STRIDE + seg * 8) * 2;
        const void* gp = g + (size_t)(row0 + row) * ld + k0 + seg * 8;
        CP_ASYNC_16(so, gp);
    }
}

// EPI: 0 = store, 2 = += resid
template <int EPI, int BN, int CHUNK, int OCC>
__global__ void __launch_bounds__(256, OCC) gemm_hmma_kernel(
    int K,
    const __half* __restrict__ A, int lda,
    const __half* __restrict__ B, int ldb,
    float* __restrict__ C, int ldc,
    const float* __restrict__ resid) {
    extern __shared__ __half smem[];
    const uint32_t sbu = smem_to_u32(smem);
    const int tid = threadIdx.x;
    const int wid = tid >> 5, lane = tid & 31;
    const int bm0 = blockIdx.y * 128, bn0 = blockIdx.x * BN;

    constexpr int STRIDE = CHUNK + 8;
    constexpr int A_ELE = 128 * STRIDE;
    constexpr int B_ELE = BN * STRIDE;
    constexpr int BUF_ELE = A_ELE + B_ELE;
    constexpr int MT = (BN == 128) ? 4 : 2;

    const int wm = (BN == 128) ? (wid >> 2) * 64 : (wid >> 1) * 32;
    const int wn = (BN == 128) ? (wid & 3) * 32 : (wid & 1) * 32;

    float acc[MT][4][4];
    #pragma unroll
    for (int i = 0; i < MT; i++)
        #pragma unroll
        for (int j = 0; j < 4; j++)
            #pragma unroll
            for (int q = 0; q < 4; q++) acc[i][j][q] = 0.f;

    const int NC = K / CHUNK;

    hmma_fill<128, CHUNK>(sbu,            A, lda, bm0, 0, tid);
    hmma_fill<BN, CHUNK>(sbu + A_ELE * 2, B, ldb, bn0, 0, tid);
    CP_ASYNC_COMMIT();

    const int a_row = ((lane >> 3) & 1) * 8 + (lane & 7);
    const int a_col = ((lane >> 4) & 1) * 8;
    const int b_row = ((lane >> 4) & 1) * 8 + (lane & 7);
    const int b_col = ((lane >> 3) & 1) * 8;

    for (int ck = 0; ck < NC; ck++) {
        const int b = ck & 1;
        CP_ASYNC_WAIT0();
        __syncthreads();
        if (ck + 1 < NC) {
            uint32_t nb = sbu + (uint32_t)((b ^ 1) * BUF_ELE) * 2;
            const int k0 = (ck + 1) * CHUNK;
            hmma_fill<128, CHUNK>(nb,            A, lda, bm0, k0, tid);
            hmma_fill<BN, CHUNK>(nb + A_ELE * 2, B, ldb, bn0, k0, tid);
            CP_ASYNC_COMMIT();
        }

        const uint32_t sA = sbu + (uint32_t)(b * BUF_ELE) * 2;
        const uint32_t sB = sA + (uint32_t)A_ELE * 2;

        #pragma unroll
        for (int kk = 0; kk < CHUNK / 16; kk++) {
            const int kc = kk * 16;
            uint32_t ah[MT][4], bh[4][2];
            #pragma unroll
            for (int mt = 0; mt < MT; mt++) {
                uint32_t off = (uint32_t)((wm + mt * 16 + a_row) * STRIDE + kc + a_col) * 2;
                ldmatrix_x4(ah[mt], sA + off);
            }
            #pragma unroll
            for (int nt2 = 0; nt2 < 2; nt2++) {
                uint32_t off = (uint32_t)((wn + nt2 * 16 + b_row) * STRIDE + kc + b_col) * 2;
                uint32_t r[4];
                ldmatrix_x4(r, sB + off);
                bh[nt2 * 2][0] = r[0]; bh[nt2 * 2][1] = r[1];
                bh[nt2 * 2 + 1][0] = r[2]; bh[nt2 * 2 + 1][1] = r[3];
            }
            #pragma unroll
            for (int mt = 0; mt < MT; mt++)
                #pragma unroll
                for (int nt = 0; nt < 4; nt++)
                    mma16816(acc[mt][nt], ah[mt], bh[nt]);
        }
        __syncthreads();
    }

    const int er = lane >> 2, ec = (lane & 3) * 2;
    #pragma unroll
    for (int mt = 0; mt < MT; mt++) {
        #pragma unroll
        for (int nt = 0; nt < 4; nt++) {
            int row = bm0 + wm + mt * 16 + er;
            int col = bn0 + wn + nt * 8 + ec;
            float2 v0 = make_float2(acc[mt][nt][0], acc[mt][nt][1]);
            float2 v1 = make_float2(acc[mt][nt][2], acc[mt][nt][3]);
            if (EPI == 2) {
                const float2 r0 = *reinterpret_cast<const float2*>(
                    resid + (size_t)row * ldc + col);
                const float2 r1 = *reinterpret_cast<const float2*>(
                    resid + (size_t)(row + 8) * ldc + col);
                v0.x += r0.x; v0.y += r0.y;
                v1.x += r1.x; v1.y += r1.y;
            }
            *reinterpret_cast<float2*>(C + (size_t)row * ldc + col) = v0;
            *reinterpret_cast<float2*>(C + (size_t)(row + 8) * ldc + col) = v1;
        }
    }
}

#define HT_SMEM(BN, CHUNK) (2 * (128 + (BN)) * ((CHUNK) + 8) * 2)
#define HT_SMEM_128_64 HT_SMEM(128, 64)     // 73,728 B  -> 2 CTAs/SM
#define HT_SMEM_64_128 HT_SMEM(64, 128)     // 104,448 B -> 1 CTA/SM

// ---------------- fused fp32 -> fp16 conversion of all weights ----------------
#define CVT_N1 (VOCAB * DMODEL)
#define CVT_N2 (NLAYER * 2 * DINNER * DMODEL)
#define CVT_N3 (NLAYER * DMODEL * DINNER)
__global__ void cvt_all_kernel(const float* __restrict__ emb,
                               const float* __restrict__ inw,
                               const float* __restrict__ ow,
                               __half* __restrict__ we16,
                               __half* __restrict__ wi16,
                               __half* __restrict__ wo16) {
    int i = (blockIdx.x * blockDim.x + threadIdx.x) * 4;
    const float* src;
    __half* dst;
    if (i < CVT_N1) {
        src = emb + i; dst = we16 + i;
    } else if (i < CVT_N1 + CVT_N2) {
        src = inw + (i - CVT_N1); dst = wi16 + (i - CVT_N1);
    } else if (i < CVT_N1 + CVT_N2 + CVT_N3) {
        src = ow + (i - CVT_N1 - CVT_N2); dst = wo16 + (i - CVT_N1 - CVT_N2);
    } else {
        return;
    }
    float4 v = *reinterpret_cast<const float4*>(src);
    *reinterpret_cast<__half2*>(dst)     = __floats2half2_rn(v.x, v.y);
    *reinterpret_cast<__half2*>(dst + 2) = __floats2half2_rn(v.z, v.w);
}

// ---------------- block reductions (loss only) ----------------
__device__ __forceinline__ float blockReduceSum(float v) {
    __shared__ float sh[9];
    int lane = threadIdx.x & 31, w = threadIdx.x >> 5;
    #pragma unroll
    for (int o = 16; o; o >>= 1) v += __shfl_xor_sync(0xffffffffu, v, o);
    if (lane == 0) sh[w] = v;
    __syncthreads();
    if (threadIdx.x == 0) {
        float s = 0.f;
        int nw = (blockDim.x + 31) >> 5;
        for (int i = 0; i < nw; i++) s += sh[i];
        sh[8] = s;
    }
    __syncthreads();
    float r = sh[8];
    __syncthreads();
    return r;
}

__device__ __forceinline__ float blockReduceMax(float v) {
    __shared__ float sh[9];
    int lane = threadIdx.x & 31, w = threadIdx.x >> 5;
    #pragma unroll
    for (int o = 16; o; o >>= 1) v = fmaxf(v, __shfl_xor_sync(0xffffffffu, v, o));
    if (lane == 0) sh[w] = v;
    __syncthreads();
    if (threadIdx.x == 0) {
        float s = -1e30f;
        int nw = (blockDim.x + 31) >> 5;
        for (int i = 0; i < nw; i++) s = fmaxf(s, sh[i]);
        sh[8] = s;
    }
    __syncthreads();
    float r = sh[8];
    __syncthreads();
    return r;
}

// ---------------- embedding ----------------
__global__ void embed_kernel(const int* __restrict__ ids,
                             const float* __restrict__ emb,
                             const float* __restrict__ pos) {
    int i = blockIdx.x * blockDim.x + threadIdx.x;
    if (i >= LSEQ * DMODEL) return;
    int t = i / DMODEL;
    int d = i - t * DMODEL;
    g_h[i] = emb[(size_t)ids[t] * DMODEL + d] + pos[i];
}

// ---------------- rmsnorm -> fp16, warp per token ----------------
__global__ void rmsnorm_kernel(const float* __restrict__ src,
                               const float* __restrict__ w,
                               __half* __restrict__ dst) {
    int warp = threadIdx.x >> 5, lane = threadIdx.x & 31;
    int t = blockIdx.x * 8 + warp;
    const float* r = src + (size_t)t * DMODEL;
    float4 v[4];
    float ss = 0.f;
    #pragma unroll
    for (int q = 0; q < 4; q++) {
        v[q] = *reinterpret_cast<const float4*>(r + (q * 32 + lane) * 4);
        ss += v[q].x * v[q].x + v[q].y * v[q].y + v[q].z * v[q].z + v[q].w * v[q].w;
    }
    #pragma unroll
    for (int o = 16; o; o >>= 1) ss += __shfl_xor_sync(0xffffffffu, ss, o);
    float sc = rsqrtf(ss * (1.0f / DMODEL) + 1e-6f);
    __half* dp = dst + (size_t)t * DMODEL;
    #pragma unroll
    for (int q = 0; q < 4; q++) {
        int idx = (q * 32 + lane) * 4;
        float4 w4 = *reinterpret_cast<const float4*>(w + idx);
        __half2 h0 = __floats2half2_rn(v[q].x * sc * w4.x, v[q].y * sc * w4.y);
        __half2 h1 = __floats2half2_rn(v[q].z * sc * w4.z, v[q].w * sc * w4.w);
        *reinterpret_cast<__half2*>(dp + idx)     = h0;
        *reinterpret_cast<__half2*>(dp + idx + 2) = h1;
    }
}

// =================================================================================
// fp32 GEMM 64x64x16 (small xproj/dt), double-buffered, 256 threads, 4x4/thread
// split-K via blockIdx.z.
// EPI: 0 = plain store, 1 = softplus(v+bias[col]) stored TRANSPOSED (C[col][row]);
//      EPI==1 blocks with blockIdx.x==0 ALSO reduce the bc split-K partials into
//      g_bcT for their 64-row slice (folds the old reduce4 kernel in).
// SUMA: A elements are the sum of 4 split-K partials at stride LSEQ*XDIM
// =================================================================================
template <int EPI, int SUMA>
__global__ void __launch_bounds__(256) gemm64_kernel(
    int Kloc,
    const float* __restrict__ A, int lda,
    const float* __restrict__ B, int ldb,
    float* __restrict__ C, int ldc, int partStride,
    const float* __restrict__ bias) {
    __shared__ float As[2][16][68];
    __shared__ float Bs[2][16][68];
    const int tid = threadIdx.x;
    const int bm0 = blockIdx.y * 64, bn0 = blockIdx.x * 64;
    const int kbase = blockIdx.z * Kloc;
    C += (size_t)blockIdx.z * partStride;
    const int PS = LSEQ * XDIM;

    // folded reduce4: bcT slice for rows [bm0, bm0+64)
    if (EPI == 1 && blockIdx.x == 0) {
        #pragma unroll
        for (int i = 0; i < 8; i++) {
            int idx = i * 256 + tid;            // 0..2047
            int s2 = idx >> 6, tl = idx & 63;
            int t = bm0 + tl;
            int b = t * XDIM + DTRANK + s2;
            g_bcT[(size_t)s2 * LSEQ + t] =
                g_xpart[b] + g_xpart[b + PS] + g_xpart[b + 2 * PS] + g_xpart[b + 3 * PS];
        }
    }

    const int lrow = tid >> 2;
    const int kq0  = (tid & 3) << 2;
    const float* Ap = A + (size_t)(bm0 + lrow) * lda + kbase + kq0;
    const float* Bp = B + (size_t)(bn0 + lrow) * ldb + kbase + kq0;

    const int ty = tid >> 4, tx = tid & 15;

    float acc[4][4];
    #pragma unroll
    for (int i = 0; i < 4; i++)
        #pragma unroll
        for (int j = 0; j < 4; j++) acc[i][j] = 0.f;

    auto loadA = [&](int off) -> float4 {
        float4 a = *reinterpret_cast<const float4*>(Ap + off);
        if (SUMA) {
            float4 p1 = *reinterpret_cast<const float4*>(Ap + off + PS);
            float4 p2 = *reinterpret_cast<const float4*>(Ap + off + 2 * PS);
            float4 p3 = *reinterpret_cast<const float4*>(Ap + off + 3 * PS);
            a.x = a.x + p1.x + p2.x + p3.x;
            a.y = a.y + p1.y + p2.y + p3.y;
            a.z = a.z + p1.z + p2.z + p3.z;
            a.w = a.w + p1.w + p2.w + p3.w;
        }
        return a;
    };

    float4 av = loadA(0);
    float4 bv = *reinterpret_cast<const float4*>(Bp);
    As[0][kq0 + 0][lrow] = av.x; As[0][kq0 + 1][lrow] = av.y;
    As[0][kq0 + 2][lrow] = av.z; As[0][kq0 + 3][lrow] = av.w;
    Bs[0][kq0 + 0][lrow] = bv.x; Bs[0][kq0 + 1][lrow] = bv.y;
    Bs[0][kq0 + 2][lrow] = bv.z; Bs[0][kq0 + 3][lrow] = bv.w;
    __syncthreads();

    const int KT = Kloc >> 4;
    for (int kt = 0; kt < KT; kt++) {
        const int cur = kt & 1, nxt = cur ^ 1;
        if (kt + 1 < KT) {
            int off = (kt + 1) << 4;
            av = loadA(off);
            bv = *reinterpret_cast<const float4*>(Bp + off);
        }
        #pragma unroll
        for (int kk = 0; kk < 16; kk++) {
            float4 a4 = *reinterpret_cast<const float4*>(&As[cur][kk][ty * 4]);
            float4 b4 = *reinterpret_cast<const float4*>(&Bs[cur][kk][tx * 4]);
            float a[4] = {a4.x, a4.y, a4.z, a4.w};
            float b[4] = {b4.x, b4.y, b4.z, b4.w};
            #pragma unroll
            for (int i = 0; i < 4; i++)
                #pragma unroll
                for (int j = 0; j < 4; j++)
                    acc[i][j] = fmaf(a[i], b[j], acc[i][j]);
        }
        if (kt + 1 < KT) {
            As[nxt][kq0 + 0][lrow] = av.x; As[nxt][kq0 + 1][lrow] = av.y;
            As[nxt][kq0 + 2][lrow] = av.z; As[nxt][kq0 + 3][lrow] = av.w;
            Bs[nxt][kq0 + 0][lrow] = bv.x; Bs[nxt][kq0 + 1][lrow] = bv.y;
            Bs[nxt][kq0 + 2][lrow] = bv.z; Bs[nxt][kq0 + 3][lrow] = bv.w;
            __syncthreads();
        }
    }

    if (EPI == 1) {
        float4 bias4 = *reinterpret_cast<const float4*>(&bias[bn0 + tx * 4]);
        float bb[4] = {bias4.x, bias4.y, bias4.z, bias4.w};
        #pragma unroll
        for (int i = 0; i < 4; i++)
            #pragma unroll
            for (int j = 0; j < 4; j++) {
                float v = acc[i][j] + bb[j];
                acc[i][j] = (v > 20.f) ? v : log1pf(expf(v));
            }
        int row0 = bm0 + ty * 4;
        #pragma unroll
        for (int j = 0; j < 4; j++) {
            int col = bn0 + tx * 4 + j;
            float4 v = make_float4(acc[0][j], acc[1][j], acc[2][j], acc[3][j]);
            *reinterpret_cast<float4*>(C + (size_t)col * ldc + row0) = v;
        }
    } else {
        #pragma unroll
        for (int i = 0; i < 4; i++) {
            int row = bm0 + ty * 4 + i;
            float* cp = C + (size_t)row * ldc + bn0 + tx * 4;
            *reinterpret_cast<float4*>(cp) =
                make_float4(acc[i][0], acc[i][1], acc[i][2], acc[i][3]);
        }
    }
}

// ---------------- depthwise causal conv (width 4) + bias + silu ----------------
__global__ void conv_silu_kernel(const float* __restrict__ cw,
                                 const float* __restrict__ cb) {
    __shared__ float su[64][33];
    const int c0 = blockIdx.x * 64;
    const int t0 = blockIdx.y * 32;
    const int tid = threadIdx.x;
    #pragma unroll
    for (int it = 0; it < 8; it++) {
        int idx = it * 256 + tid;
        int cl = idx & 63, tl = idx >> 6;
        int c = c0 + cl, t = t0 + tl;
        float v = cb[c];
        #pragma unroll
        for (int k = 0; k < DCONV; k++) {
            int tt = t - (DCONV - 1) + k;
            if (tt >= 0)
                v = fmaf(g_xz[(size_t)tt * (2 * DINNER) + c], cw[c * DCONV + k], v);
        }
        float s = v / (1.f + expf(-v));
        g_u[(size_t)t * DINNER + c] = s;
        su[cl][tl] = s;
    }
    __syncthreads();
    #pragma unroll
    for (int it = 0; it < 8; it++) {
        int cl = it * 8 + (tid >> 5);
        int tl = tid & 31;
        g_uT[(size_t)(c0 + cl) * LSEQ + (t0 + tl)] = su[cl][tl];
    }
}

// ---------------- selective scan (fused y-combine, emits fp16) ----------------
__global__ void scan_kernel(const float* __restrict__ deltaT,
                            const float* __restrict__ uT,
                            const float* __restrict__ bcT,
                            const float* __restrict__ A_log,
                            const float* __restrict__ xz,
                            const float* __restrict__ Dp,
                            __half* __restrict__ yout) {
    int warp = threadIdx.x >> 5;
    int lane = threadIdx.x & 31;
    int half = lane >> 4;
    int s    = lane & 15;
    int ch   = blockIdx.x * 8 + warp * 2 + half;

    float A2 = -__expf(A_log[ch * DSTATE + s]) * 1.44269504088896f;
    float dpv = Dp[ch];
    float h = 0.f;
    const float* dT  = deltaT + (size_t)ch * LSEQ;
    const float* uTp = uT + (size_t)ch * LSEQ;
    const float* bT  = bcT + (size_t)s * LSEQ;
    const float* cT  = bcT + (size_t)(DSTATE + s) * LSEQ;

    for (int t0 = 0; t0 < LSEQ; t0 += 16) {
        float dv[16], uv[16], bv[16], cv[16];
        #pragma unroll
        for (int q = 0; q < 4; q++) {
            float4 d4 = *reinterpret_cast<const float4*>(dT + t0 + q * 4);
            float4 u4 = *reinterpret_cast<const float4*>(uTp + t0 + q * 4);
            float4 b4 = *reinterpret_cast<const float4*>(bT + t0 + q * 4);
            float4 c4 = *reinterpret_cast<const float4*>(cT + t0 + q * 4);
            dv[q*4+0]=d4.x; dv[q*4+1]=d4.y; dv[q*4+2]=d4.z; dv[q*4+3]=d4.w;
            uv[q*4+0]=u4.x; uv[q*4+1]=u4.y; uv[q*4+2]=u4.z; uv[q*4+3]=u4.w;
            bv[q*4+0]=b4.x; bv[q*4+1]=b4.y; bv[q*4+2]=b4.z; bv[q*4+3]=b4.w;
            cv[q*4+0]=c4.x; cv[q*4+1]=c4.y; cv[q*4+2]=c4.z; cv[q*4+3]=c4.w;
        }
        float p[16];
        #pragma unroll
        for (int j = 0; j < 16; j++) {
            float dA  = exp2f(dv[j] * A2);
            float dbu = dv[j] * uv[j] * bv[j];
            h = fmaf(dA, h, dbu);
            p[j] = h * cv[j];
        }
        float out = 0.f, uo = 0.f;
        #pragma unroll
        for (int j = 0; j < 16; j++) {
            float v = p[j];
            v += __shfl_xor_sync(0xffffffffu, v, 1);
            v += __shfl_xor_sync(0xffffffffu, v, 2);
            v += __shfl_xor_sync(0xffffffffu, v, 4);
            v += __shfl_xor_sync(0xffffffffu, v, 8);
            if (s == j) { out = v; uo = uv[j]; }
        }
        int t = t0 + s;
        float zz = xz[(size_t)t * (2 * DINNER) + DINNER + ch];
        float sz = zz / (1.f + expf(-zz));
        yout[(size_t)t * DINNER + ch] = __float2half((out + uo * dpv) * sz);
    }
}

// ---------------- cross-entropy loss (fused final divide via ticket) ----------------
__global__ void loss_kernel(const int* __restrict__ labels,
                            const float* __restrict__ logits,
                            float* __restrict__ out, int idx) {
    int t = blockIdx.x;
    const float* row = logits + (size_t)t * VOCAB;
    float mx = -1e30f;
    for (int j = threadIdx.x; j < VOCAB; j += 256) mx = fmaxf(mx, row[j]);
    mx = blockReduceMax(mx);
    float sum = 0.f;
    for (int j = threadIdx.x; j < VOCAB; j += 256) sum += expf(row[j] - mx);
    sum = blockReduceSum(sum);
    if (threadIdx.x == 0) {
        int tgt = labels[t + 1];
        if (tgt != -100) {
            float lp = row[tgt] - mx - logf(sum);
            atomicAdd(&g_loss[0], -lp);
            atomicAdd(&g_loss[1], 1.f);
        }
        __threadfence();
        int ticket = atomicAdd(reinterpret_cast<int*>(&g_loss[2]), 1);
        if (ticket == (int)gridDim.x - 1) {
            out[idx] = g_loss[0] / fmaxf(g_loss[1], 1.f);
        }
    }
}

// ---------------- driver ----------------
extern "C" void kernel_launch(void* const* d_in, const int* in_sizes, int n_in,
                              void* d_out, int out_size) {
    const int*   ids    = (const int*)  d_in[0];
    const int*   labels = (const int*)  d_in[1];
    const float* emb    = (const float*)d_in[2];
    const float* pos    = (const float*)d_in[3];
    const float* fnw    = (const float*)d_in[4];
    const float* nw     = (const float*)d_in[5];
    const float* inw    = (const float*)d_in[6];
    const float* cw     = (const float*)d_in[7];
    const float* cb     = (const float*)d_in[8];
    const float* xw     = (const float*)d_in[9];
    const float* dw     = (const float*)d_in[10];
    const float* db     = (const float*)d_in[11];
    const float* alog   = (const float*)d_in[12];
    const float* dp     = (const float*)d_in[13];
    const float* ow     = (const float*)d_in[14];
    float* out = (float*)d_out;

    float *ph, *pxz, *pu, *puT, *pxpart, *pbcT, *pdT, *ploss;
    __half *pa16, *pwe16, *pwi16, *pwo16;
    cudaGetSymbolAddress((void**)&ph,     g_h);
    cudaGetSymbolAddress((void**)&pxz,    g_xz);
    cudaGetSymbolAddress((void**)&pu,     g_u);
    cudaGetSymbolAddress((void**)&puT,    g_uT);
    cudaGetSymbolAddress((void**)&pxpart, g_xpart);
    cudaGetSymbolAddress((void**)&pbcT,   g_bcT);
    cudaGetSymbolAddress((void**)&pdT,    g_deltaT);
    cudaGetSymbolAddress((void**)&ploss,  g_loss);
    cudaGetSymbolAddress((void**)&pa16,   g_a16);
    cudaGetSymbolAddress((void**)&pwe16,  g_wemb16);
    cudaGetSymbolAddress((void**)&pwi16,  g_win16);
    cudaGetSymbolAddress((void**)&pwo16,  g_wout16);

    cudaFuncSetAttribute((const void*)gemm_hmma_kernel<0, 128, 64, 2>,
        cudaFuncAttributeMaxDynamicSharedMemorySize, HT_SMEM_128_64);
    cudaFuncSetAttribute((const void*)gemm_hmma_kernel<2, 64, 128, 1>,
        cudaFuncAttributeMaxDynamicSharedMemorySize, HT_SMEM_64_128);

    embed_kernel<<<(LSEQ * DMODEL + 255) / 256, 256>>>(ids, emb, pos);
    {
        int total = CVT_N1 + CVT_N2 + CVT_N3;
        cvt_all_kernel<<<(total / 4 + 255) / 256, 256>>>(
            emb, inw, ow, pwe16, pwi16, pwo16);
    }

    for (int l = 0; l < NLAYER; l++) {
        const float* nw_l  = nw   + (size_t)l * DMODEL;
        const float* cw_l  = cw   + (size_t)l * DINNER * DCONV;
        const float* cb_l  = cb   + (size_t)l * DINNER;
        const float* xw_l  = xw   + (size_t)l * XDIM * DINNER;
        const float* dw_l  = dw   + (size_t)l * DINNER * DTRANK;
        const float* db_l  = db   + (size_t)l * DINNER;
        const float* al_l  = alog + (size_t)l * DINNER * DSTATE;
        const float* dp_l  = dp   + (size_t)l * DINNER;
        const __half* wi_l = pwi16 + (size_t)l * 2 * DINNER * DMODEL;
        const __half* wo_l = pwo16 + (size_t)l * DMODEL * DINNER;

        // x = rmsnorm(h) -> fp16 (warp per token)
        rmsnorm_kernel<<<LSEQ / 8, 256>>>(ph, nw_l, pa16);
        // xz = x @ in_w^T  [2048 x 2048], K=512 (HMMA)
        gemm_hmma_kernel<0, 128, 64, 2>
            <<<dim3(2 * DINNER / 128, LSEQ / 128), 256, HT_SMEM_128_64>>>(
            DMODEL, pa16, DMODEL, wi_l, DMODEL, pxz, 2 * DINNER, nullptr);
        // u = silu(causal depthwise conv(xi) + b)  (u and u_T, both coalesced)
        conv_silu_kernel<<<dim3(DINNER / 64, LSEQ / 32), 256>>>(cw_l, cb_l);
        // xdbl partials = u @ xproj_w^T  [2048 x 64], K=1024, split-K x4 (fp32)
        gemm64_kernel<0, 0><<<dim3(1, LSEQ / 64, 4), 256>>>(
            DINNER / 4, pu, DINNER, xw_l, DINNER, pxpart, XDIM, LSEQ * XDIM, nullptr);
        // delta_T = softplus((sum dt partials) @ dt_w^T + dt_b)^T; also reduces bcT
        gemm64_kernel<1, 1><<<dim3(DINNER / 64, LSEQ / 64), 256>>>(
            DTRANK, pxpart, XDIM, dw_l, DTRANK, pdT, LSEQ, 0, db_l);
        // selective scan + fused (y + u*Dp)*silu(z) -> fp16
        scan_kernel<<<DINNER / 8, 128>>>(pdT, puT, pbcT, al_l, pxz, dp_l, pa16);
        // h = h + yf @ out_w^T  [2048 x 512], K=1024 (HMMA)
        gemm_hmma_kernel<2, 64, 128, 1>
            <<<dim3(DMODEL / 64, LSEQ / 128), 256, HT_SMEM_64_128>>>(
            DINNER, pa16, DINNER, wo_l, DINNER, ph, DMODEL, ph);
    }

    // final norm + logits (HMMA)
    rmsnorm_kernel<<<LSEQ / 8, 256>>>(ph, fnw, pa16);
    gemm_hmma_kernel<0, 128, 64, 2>
        <<<dim3(VOCAB / 128, LSEQ / 128), 256, HT_SMEM_128_64>>>(
        DMODEL, pa16, DMODEL, pwe16, DMODEL, out, VOCAB, nullptr);

    // loss (init via memset node; final divide fused via last-block ticket)
    cudaMemsetAsync(ploss, 0, 4 * sizeof(float));
    loss_kernel<<<LSEQ - 1, 256>>>(labels, out, out, out_size - 1);
}

// round 16
// speedup vs baseline: 1.2187x; 1.2127x over previous
#include <cuda_runtime.h>
#include <cuda_fp16.h>
#include <math.h>
#include <stdint.h>

#define LSEQ   2048
#define DMODEL 512
#define NLAYER 8
#define DSTATE 16
#define DCONV  4
#define DINNER 1024
#define DTRANK 32
#define VOCAB  4096
#define XDIM   64   // DT_RANK + 2*D_STATE

// ---------------- scratch (static device globals; no allocation) ----------------
__device__ float g_h[LSEQ * DMODEL];
__device__ float g_xz[LSEQ * 2 * DINNER];
__device__ float g_u[LSEQ * DINNER];
__device__ float g_uT[DINNER * LSEQ];
__device__ float g_xpart[4 * LSEQ * XDIM];
__device__ float g_bcT[2 * DSTATE * LSEQ];  // B rows [0..15], C rows [16..31], transposed
__device__ float g_deltaT[DINNER * LSEQ];
__device__ float g_loss[2];

// fp16 buffers
__device__ __half g_a16[LSEQ * DINNER];
__device__ __half g_wemb16[VOCAB * DMODEL];
__device__ __half g_win16[NLAYER * 2 * DINNER * DMODEL];
__device__ __half g_wout16[NLAYER * DMODEL * DINNER];

// =============================== PTX helpers ===============================
__device__ __forceinline__ uint32_t smem_to_u32(const void* p) {
    uint32_t a;
    asm("{ .reg .u64 t; cvta.to.shared.u64 t, %1; cvt.u32.u64 %0, t; }"
        : "=r"(a) : "l"(p));
    return a;
}

#define CP_ASYNC_16(dst, src) \
    asm volatile("cp.async.cg.shared.global [%0], [%1], 16;" \
        :: "r"(dst), "l"(src) : "memory")
#define CP_ASYNC_COMMIT() asm volatile("cp.async.commit_group;" ::: "memory")
#define CP_ASYNC_WAIT0()  asm volatile("cp.async.wait_group 0;" ::: "memory")

__device__ __forceinline__ void ldmatrix_x4(uint32_t* r, uint32_t addr) {
    asm volatile("ldmatrix.sync.aligned.m8n8.x4.shared.b16 {%0,%1,%2,%3}, [%4];"
        : "=r"(r[0]), "=r"(r[1]), "=r"(r[2]), "=r"(r[3]) : "r"(addr));
}

__device__ __forceinline__ void mma16816(float* c, const uint32_t* a, const uint32_t* b) {
    asm volatile(
        "mma.sync.aligned.m16n8k16.row.col.f32.f16.f16.f32 "
        "{%0,%1,%2,%3}, {%4,%5,%6,%7}, {%8,%9}, {%0,%1,%2,%3};"
        : "+f"(c[0]), "+f"(c[1]), "+f"(c[2]), "+f"(c[3])
        : "r"(a[0]), "r"(a[1]), "r"(a[2]), "r"(a[3]), "r"(b[0]), "r"(b[1]));
}

// ======================= fp16 HMMA GEMM (r11 config — best known) =======================
// C[M,N] = A[M,K] * B[N,K]^T, fp16 in, fp32 acc.
// CTA tile 128xBN, K chunks of CHUNK, cp.async double buffer, OCC CTAs/SM.
// 256 threads = 8 warps; BN=128: 2m x 4n (warp tile 64x32); BN=64: 4m x 2n (32x32).
// smem row stride = CHUNK+8 fp16 -> ldmatrix conflict-free for CHUNK 64/128.

template <int ROWS, int CHUNK>
__device__ __forceinline__ void hmma_fill(
    uint32_t sdst, const __half* __restrict__ g, int ld, int row0, int k0, int tid) {
    constexpr int STRIDE = CHUNK + 8;
    constexpr int SEGS = CHUNK / 8;
    #pragma unroll
    for (int r = 0; r < ROWS * SEGS / 256; r++) {
        int idx = r * 256 + tid;
        int row = idx / SEGS, seg = idx % SEGS;
        uint32_t so = sdst + (uint32_t)(row * STRIDE + seg * 8) * 2;
        const void* gp = g + (size_t)(row0 + row) * ld + k0 + seg * 8;
        CP_ASYNC_16(so, gp);
    }
}

// EPI: 0 = store, 2 = += resid
template <int EPI, int BN, int CHUNK, int OCC>
__global__ void __launch_bounds__(256, OCC) gemm_hmma_kernel(
    int K,
    const __half* __restrict__ A, int lda,
    const __half* __restrict__ B, int ldb,
    float* __restrict__ C, int ldc,
    const float* __restrict__ resid) {
    extern __shared__ __half smem[];
    const uint32_t sbu = smem_to_u32(smem);
    const int tid = threadIdx.x;
    const int wid = tid >> 5, lane = tid & 31;
    const int bm0 = blockIdx.y * 128, bn0 = blockIdx.x * BN;

    constexpr int STRIDE = CHUNK + 8;
    constexpr int A_ELE = 128 * STRIDE;
    constexpr int B_ELE = BN * STRIDE;
    constexpr int BUF_ELE = A_ELE + B_ELE;
    constexpr int MT = (BN == 128) ? 4 : 2;

    const int wm = (BN == 128) ? (wid >> 2) * 64 : (wid >> 1) * 32;
    const int wn = (BN == 128) ? (wid & 3) * 32 : (wid & 1) * 32;

    float acc[MT][4][4];
    #pragma unroll
    for (int i = 0; i < MT; i++)
        #pragma unroll
        for (int j = 0; j < 4; j++)
            #pragma unroll
            for (int q = 0; q < 4; q++) acc[i][j][q] = 0.f;

    const int NC = K / CHUNK;

    hmma_fill<128, CHUNK>(sbu,            A, lda, bm0, 0, tid);
    hmma_fill<BN, CHUNK>(sbu + A_ELE * 2, B, ldb, bn0, 0, tid);
    CP_ASYNC_COMMIT();

    const int a_row = ((lane >> 3) & 1) * 8 + (lane & 7);
    const int a_col = ((lane >> 4) & 1) * 8;
    const int b_row = ((lane >> 4) & 1) * 8 + (lane & 7);
    const int b_col = ((lane >> 3) & 1) * 8;

    for (int ck = 0; ck < NC; ck++) {
        const int b = ck & 1;
        CP_ASYNC_WAIT0();
        __syncthreads();
        if (ck + 1 < NC) {
            uint32_t nb = sbu + (uint32_t)((b ^ 1) * BUF_ELE) * 2;
            const int k0 = (ck + 1) * CHUNK;
            hmma_fill<128, CHUNK>(nb,            A, lda, bm0, k0, tid);
            hmma_fill<BN, CHUNK>(nb + A_ELE * 2, B, ldb, bn0, k0, tid);
            CP_ASYNC_COMMIT();
        }

        const uint32_t sA = sbu + (uint32_t)(b * BUF_ELE) * 2;
        const uint32_t sB = sA + (uint32_t)A_ELE * 2;

        #pragma unroll
        for (int kk = 0; kk < CHUNK / 16; kk++) {
            const int kc = kk * 16;
            uint32_t ah[MT][4], bh[4][2];
            #pragma unroll
            for (int mt = 0; mt < MT; mt++) {
                uint32_t off = (uint32_t)((wm + mt * 16 + a_row) * STRIDE + kc + a_col) * 2;
                ldmatrix_x4(ah[mt], sA + off);
            }
            #pragma unroll
            for (int nt2 = 0; nt2 < 2; nt2++) {
                uint32_t off = (uint32_t)((wn + nt2 * 16 + b_row) * STRIDE + kc + b_col) * 2;
                uint32_t r[4];
                ldmatrix_x4(r, sB + off);
                bh[nt2 * 2][0] = r[0]; bh[nt2 * 2][1] = r[1];
                bh[nt2 * 2 + 1][0] = r[2]; bh[nt2 * 2 + 1][1] = r[3];
            }
            #pragma unroll
            for (int mt = 0; mt < MT; mt++)
                #pragma unroll
                for (int nt = 0; nt < 4; nt++)
                    mma16816(acc[mt][nt], ah[mt], bh[nt]);
        }
        __syncthreads();
    }

    const int er = lane >> 2, ec = (lane & 3) * 2;
    #pragma unroll
    for (int mt = 0; mt < MT; mt++) {
        #pragma unroll
        for (int nt = 0; nt < 4; nt++) {
            int row = bm0 + wm + mt * 16 + er;
            int col = bn0 + wn + nt * 8 + ec;
            float2 v0 = make_float2(acc[mt][nt][0], acc[mt][nt][1]);
            float2 v1 = make_float2(acc[mt][nt][2], acc[mt][nt][3]);
            if (EPI == 2) {
                const float2 r0 = *reinterpret_cast<const float2*>(
                    resid + (size_t)row * ldc + col);
                const float2 r1 = *reinterpret_cast<const float2*>(
                    resid + (size_t)(row + 8) * ldc + col);
                v0.x += r0.x; v0.y += r0.y;
                v1.x += r1.x; v1.y += r1.y;
            }
            *reinterpret_cast<float2*>(C + (size_t)row * ldc + col) = v0;
            *reinterpret_cast<float2*>(C + (size_t)(row + 8) * ldc + col) = v1;
        }
    }
}

#define HT_SMEM(BN, CHUNK) (2 * (128 + (BN)) * ((CHUNK) + 8) * 2)
#define HT_SMEM_128_64 HT_SMEM(128, 64)     // 73,728 B  -> 2 CTAs/SM
#define HT_SMEM_64_128 HT_SMEM(64, 128)     // 104,448 B -> 1 CTA/SM

// ---------------- fused fp32 -> fp16 conversion of all weights ----------------
#define CVT_N1 (VOCAB * DMODEL)
#define CVT_N2 (NLAYER * 2 * DINNER * DMODEL)
#define CVT_N3 (NLAYER * DMODEL * DINNER)
__global__ void cvt_all_kernel(const float* __restrict__ emb,
                               const float* __restrict__ inw,
                               const float* __restrict__ ow,
                               __half* __restrict__ we16,
                               __half* __restrict__ wi16,
                               __half* __restrict__ wo16) {
    int i = (blockIdx.x * blockDim.x + threadIdx.x) * 4;
    const float* src;
    __half* dst;
    if (i < CVT_N1) {
        src = emb + i; dst = we16 + i;
    } else if (i < CVT_N1 + CVT_N2) {
        src = inw + (i - CVT_N1); dst = wi16 + (i - CVT_N1);
    } else if (i < CVT_N1 + CVT_N2 + CVT_N3) {
        src = ow + (i - CVT_N1 - CVT_N2); dst = wo16 + (i - CVT_N1 - CVT_N2);
    } else {
        return;
    }
    float4 v = *reinterpret_cast<const float4*>(src);
    *reinterpret_cast<__half2*>(dst)     = __floats2half2_rn(v.x, v.y);
    *reinterpret_cast<__half2*>(dst + 2) = __floats2half2_rn(v.z, v.w);
}

// ---------------- block reductions (loss only) ----------------
__device__ __forceinline__ float blockReduceSum(float v) {
    __shared__ float sh[9];
    int lane = threadIdx.x & 31, w = threadIdx.x >> 5;
    #pragma unroll
    for (int o = 16; o; o >>= 1) v += __shfl_xor_sync(0xffffffffu, v, o);
    if (lane == 0) sh[w] = v;
    __syncthreads();
    if (threadIdx.x == 0) {
        float s = 0.f;
        int nw = (blockDim.x + 31) >> 5;
        for (int i = 0; i < nw; i++) s += sh[i];
        sh[8] = s;
    }
    __syncthreads();
    float r = sh[8];
    __syncthreads();
    return r;
}

__device__ __forceinline__ float blockReduceMax(float v) {
    __shared__ float sh[9];
    int lane = threadIdx.x & 31, w = threadIdx.x >> 5;
    #pragma unroll
    for (int o = 16; o; o >>= 1) v = fmaxf(v, __shfl_xor_sync(0xffffffffu, v, o));
    if (lane == 0) sh[w] = v;
    __syncthreads();
    if (threadIdx.x == 0) {
        float s = -1e30f;
        int nw = (blockDim.x + 31) >> 5;
        for (int i = 0; i < nw; i++) s = fmaxf(s, sh[i]);
        sh[8] = s;
    }
    __syncthreads();
    float r = sh[8];
    __syncthreads();
    return r;
}

// ---------------- embedding ----------------
__global__ void embed_kernel(const int* __restrict__ ids,
                             const float* __restrict__ emb,
                             const float* __restrict__ pos) {
    int i = blockIdx.x * blockDim.x + threadIdx.x;
    if (i >= LSEQ * DMODEL) return;
    int t = i / DMODEL;
    int d = i - t * DMODEL;
    g_h[i] = emb[(size_t)ids[t] * DMODEL + d] + pos[i];
}

// ---------------- rmsnorm -> fp16, warp per token ----------------
__global__ void rmsnorm_kernel(const float* __restrict__ src,
                               const float* __restrict__ w,
                               __half* __restrict__ dst) {
    int warp = threadIdx.x >> 5, lane = threadIdx.x & 31;
    int t = blockIdx.x * 8 + warp;
    const float* r = src + (size_t)t * DMODEL;
    float4 v[4];
    float ss = 0.f;
    #pragma unroll
    for (int q = 0; q < 4; q++) {
        v[q] = *reinterpret_cast<const float4*>(r + (q * 32 + lane) * 4);
        ss += v[q].x * v[q].x + v[q].y * v[q].y + v[q].z * v[q].z + v[q].w * v[q].w;
    }
    #pragma unroll
    for (int o = 16; o; o >>= 1) ss += __shfl_xor_sync(0xffffffffu, ss, o);
    float sc = rsqrtf(ss * (1.0f / DMODEL) + 1e-6f);
    __half* dp = dst + (size_t)t * DMODEL;
    #pragma unroll
    for (int q = 0; q < 4; q++) {
        int idx = (q * 32 + lane) * 4;
        float4 w4 = *reinterpret_cast<const float4*>(w + idx);
        __half2 h0 = __floats2half2_rn(v[q].x * sc * w4.x, v[q].y * sc * w4.y);
        __half2 h1 = __floats2half2_rn(v[q].z * sc * w4.z, v[q].w * sc * w4.w);
        *reinterpret_cast<__half2*>(dp + idx)     = h0;
        *reinterpret_cast<__half2*>(dp + idx + 2) = h1;
    }
}

// =================================================================================
// fp32 GEMM 64x64x16 (small xproj/dt), double-buffered, 256 threads, 4x4/thread
// split-K via blockIdx.z.
// EPI: 0 = plain store, 1 = softplus(v+bias[col]) stored TRANSPOSED (C[col][row])
// SUMA: A elements are the sum of 4 split-K partials at stride LSEQ*XDIM
// =================================================================================
template <int EPI, int SUMA>
__global__ void __launch_bounds__(256) gemm64_kernel(
    int Kloc,
    const float* __restrict__ A, int lda,
    const float* __restrict__ B, int ldb,
    float* __restrict__ C, int ldc, int partStride,
    const float* __restrict__ bias) {
    __shared__ float As[2][16][68];
    __shared__ float Bs[2][16][68];
    const int tid = threadIdx.x;
    const int bm0 = blockIdx.y * 64, bn0 = blockIdx.x * 64;
    const int kbase = blockIdx.z * Kloc;
    C += (size_t)blockIdx.z * partStride;

    const int lrow = tid >> 2;
    const int kq0  = (tid & 3) << 2;
    const float* Ap = A + (size_t)(bm0 + lrow) * lda + kbase + kq0;
    const float* Bp = B + (size_t)(bn0 + lrow) * ldb + kbase + kq0;
    const int PS = LSEQ * XDIM;

    const int ty = tid >> 4, tx = tid & 15;

    float acc[4][4];
    #pragma unroll
    for (int i = 0; i < 4; i++)
        #pragma unroll
        for (int j = 0; j < 4; j++) acc[i][j] = 0.f;

    auto loadA = [&](int off) -> float4 {
        float4 a = *reinterpret_cast<const float4*>(Ap + off);
        if (SUMA) {
            float4 p1 = *reinterpret_cast<const float4*>(Ap + off + PS);
            float4 p2 = *reinterpret_cast<const float4*>(Ap + off + 2 * PS);
            float4 p3 = *reinterpret_cast<const float4*>(Ap + off + 3 * PS);
            a.x = a.x + p1.x + p2.x + p3.x;
            a.y = a.y + p1.y + p2.y + p3.y;
            a.z = a.z + p1.z + p2.z + p3.z;
            a.w = a.w + p1.w + p2.w + p3.w;
        }
        return a;
    };

    float4 av = loadA(0);
    float4 bv = *reinterpret_cast<const float4*>(Bp);
    As[0][kq0 + 0][lrow] = av.x; As[0][kq0 + 1][lrow] = av.y;
    As[0][kq0 + 2][lrow] = av.z; As[0][kq0 + 3][lrow] = av.w;
    Bs[0][kq0 + 0][lrow] = bv.x; Bs[0][kq0 + 1][lrow] = bv.y;
    Bs[0][kq0 + 2][lrow] = bv.z; Bs[0][kq0 + 3][lrow] = bv.w;
    __syncthreads();

    const int KT = Kloc >> 4;
    for (int kt = 0; kt < KT; kt++) {
        const int cur = kt & 1, nxt = cur ^ 1;
        if (kt + 1 < KT) {
            int off = (kt + 1) << 4;
            av = loadA(off);
            bv = *reinterpret_cast<const float4*>(Bp + off);
        }
        #pragma unroll
        for (int kk = 0; kk < 16; kk++) {
            float4 a4 = *reinterpret_cast<const float4*>(&As[cur][kk][ty * 4]);
            float4 b4 = *reinterpret_cast<const float4*>(&Bs[cur][kk][tx * 4]);
            float a[4] = {a4.x, a4.y, a4.z, a4.w};
            float b[4] = {b4.x, b4.y, b4.z, b4.w};
            #pragma unroll
            for (int i = 0; i < 4; i++)
                #pragma unroll
                for (int j = 0; j < 4; j++)
                    acc[i][j] = fmaf(a[i], b[j], acc[i][j]);
        }
        if (kt + 1 < KT) {
            As[nxt][kq0 + 0][lrow] = av.x; As[nxt][kq0 + 1][lrow] = av.y;
            As[nxt][kq0 + 2][lrow] = av.z; As[nxt][kq0 + 3][lrow] = av.w;
            Bs[nxt][kq0 + 0][lrow] = bv.x; Bs[nxt][kq0 + 1][lrow] = bv.y;
            Bs[nxt][kq0 + 2][lrow] = bv.z; Bs[nxt][kq0 + 3][lrow] = bv.w;
            __syncthreads();
        }
    }

    if (EPI == 1) {
        float4 bias4 = *reinterpret_cast<const float4*>(&bias[bn0 + tx * 4]);
        float bb[4] = {bias4.x, bias4.y, bias4.z, bias4.w};
        #pragma unroll
        for (int i = 0; i < 4; i++)
            #pragma unroll
            for (int j = 0; j < 4; j++) {
                float v = acc[i][j] + bb[j];
                acc[i][j] = (v > 20.f) ? v : log1pf(expf(v));
            }
        int row0 = bm0 + ty * 4;
        #pragma unroll
        for (int j = 0; j < 4; j++) {
            int col = bn0 + tx * 4 + j;
            float4 v = make_float4(acc[0][j], acc[1][j], acc[2][j], acc[3][j]);
            *reinterpret_cast<float4*>(C + (size_t)col * ldc + row0) = v;
        }
    } else {
        #pragma unroll
        for (int i = 0; i < 4; i++) {
            int row = bm0 + ty * 4 + i;
            float* cp = C + (size_t)row * ldc + bn0 + tx * 4;
            *reinterpret_cast<float4*>(cp) =
                make_float4(acc[i][0], acc[i][1], acc[i][2], acc[i][3]);
        }
    }
}

// ---------------- reduce the 4 split-K partials: bcT only ----------------
__global__ void reduce4_kernel() {
    int j = blockIdx.x * blockDim.x + threadIdx.x;
    const int NB = 2 * DSTATE * LSEQ;   // 65536
    const int PS = LSEQ * XDIM;
    if (j >= NB) return;
    int s2 = j >> 11, t = j & (LSEQ - 1);
    int b = t * XDIM + DTRANK + s2;
    g_bcT[j] = g_xpart[b] + g_xpart[b + PS] + g_xpart[b + 2 * PS] + g_xpart[b + 3 * PS];
}

// ---------------- depthwise causal conv (width 4) + bias + silu ----------------
__global__ void conv_silu_kernel(const float* __restrict__ cw,
                                 const float* __restrict__ cb) {
    __shared__ float su[64][33];
    const int c0 = blockIdx.x * 64;
    const int t0 = blockIdx.y * 32;
    const int tid = threadIdx.x;
    #pragma unroll
    for (int it = 0; it < 8; it++) {
        int idx = it * 256 + tid;
        int cl = idx & 63, tl = idx >> 6;
        int c = c0 + cl, t = t0 + tl;
        float v = cb[c];
        #pragma unroll
        for (int k = 0; k < DCONV; k++) {
            int tt = t - (DCONV - 1) + k;
            if (tt >= 0)
                v = fmaf(g_xz[(size_t)tt * (2 * DINNER) + c], cw[c * DCONV + k], v);
        }
        float s = v / (1.f + expf(-v));
        g_u[(size_t)t * DINNER + c] = s;
        su[cl][tl] = s;
    }
    __syncthreads();
    #pragma unroll
    for (int it = 0; it < 8; it++) {
        int cl = it * 8 + (tid >> 5);
        int tl = tid & 31;
        g_uT[(size_t)(c0 + cl) * LSEQ + (t0 + tl)] = su[cl][tl];
    }
}

// ---------------- selective scan (fused y-combine, emits fp16) ----------------
// transpose-reduce: 15 shfls per 16-step chunk instead of 64.
__global__ void scan_kernel(const float* __restrict__ deltaT,
                            const float* __restrict__ uT,
                            const float* __restrict__ bcT,
                            const float* __restrict__ A_log,
                            const float* __restrict__ xz,
                            const float* __restrict__ Dp,
                            __half* __restrict__ yout) {
    int warp = threadIdx.x >> 5;
    int lane = threadIdx.x & 31;
    int half = lane >> 4;
    int s    = lane & 15;
    int ch   = blockIdx.x * 8 + warp * 2 + half;

    float A2 = -__expf(A_log[ch * DSTATE + s]) * 1.44269504088896f;
    float dpv = Dp[ch];
    float h = 0.f;
    const float* dT  = deltaT + (size_t)ch * LSEQ;
    const float* uTp = uT + (size_t)ch * LSEQ;
    const float* bT  = bcT + (size_t)s * LSEQ;
    const float* cT  = bcT + (size_t)(DSTATE + s) * LSEQ;

    const bool h8 = (s & 8), h4 = (s & 4), h2 = (s & 2), h1 = (s & 1);

    for (int t0 = 0; t0 < LSEQ; t0 += 16) {
        float dv[16], uv[16], bv[16], cv[16];
        #pragma unroll
        for (int q = 0; q < 4; q++) {
            float4 d4 = *reinterpret_cast<const float4*>(dT + t0 + q * 4);
            float4 u4 = *reinterpret_cast<const float4*>(uTp + t0 + q * 4);
            float4 b4 = *reinterpret_cast<const float4*>(bT + t0 + q * 4);
            float4 c4 = *reinterpret_cast<const float4*>(cT + t0 + q * 4);
            dv[q*4+0]=d4.x; dv[q*4+1]=d4.y; dv[q*4+2]=d4.z; dv[q*4+3]=d4.w;
            uv[q*4+0]=u4.x; uv[q*4+1]=u4.y; uv[q*4+2]=u4.z; uv[q*4+3]=u4.w;
            bv[q*4+0]=b4.x; bv[q*4+1]=b4.y; bv[q*4+2]=b4.z; bv[q*4+3]=b4.w;
            cv[q*4+0]=c4.x; cv[q*4+1]=c4.y; cv[q*4+2]=c4.z; cv[q*4+3]=c4.w;
        }
        float p[16];
        #pragma unroll
        for (int j = 0; j < 16; j++) {
            float dA  = exp2f(dv[j] * A2);
            float dbu = dv[j] * uv[j] * bv[j];
            h = fmaf(dA, h, dbu);
            p[j] = h * cv[j];
        }
        // transpose-reduce across the 16 state lanes:
        // after round o, lane s holds partial sums for logical t-offsets
        // matching its own bits; final: lane s holds out[t0+s].
        float q8[8];
        #pragma unroll
        for (int j = 0; j < 8; j++) {
            float keep = h8 ? p[j + 8] : p[j];
            float send = h8 ? p[j] : p[j + 8];
            q8[j] = keep + __shfl_xor_sync(0xffffffffu, send, 8);
        }
        float q4[4];
        #pragma unroll
        for (int j = 0; j < 4; j++) {
            float keep = h4 ? q8[j + 4] : q8[j];
            float send = h4 ? q8[j] : q8[j + 4];
            q4[j] = keep + __shfl_xor_sync(0xffffffffu, send, 4);
        }
        float q2[2];
        #pragma unroll
        for (int j = 0; j < 2; j++) {
            float keep = h2 ? q4[j + 2] : q4[j];
            float send = h2 ? q4[j] : q4[j + 2];
            q2[j] = keep + __shfl_xor_sync(0xffffffffu, send, 2);
        }
        float keep1 = h1 ? q2[1] : q2[0];
        float send1 = h1 ? q2[0] : q2[1];
        float out = keep1 + __shfl_xor_sync(0xffffffffu, send1, 1);

        float uo = 0.f;
        #pragma unroll
        for (int j = 0; j < 16; j++)
            if (s == j) uo = uv[j];

        int t = t0 + s;
        float zz = xz[(size_t)t * (2 * DINNER) + DINNER + ch];
        float sz = zz / (1.f + expf(-zz));
        yout[(size_t)t * DINNER + ch] = __float2half((out + uo * dpv) * sz);
    }
}

// ---------------- cross-entropy loss over logits ----------------
__global__ void loss_init_kernel() { g_loss[0] = 0.f; g_loss[1] = 0.f; }

__global__ void loss_kernel(const int* __restrict__ labels,
                            const float* __restrict__ logits) {
    int t = blockIdx.x;
    const float* row = logits + (size_t)t * VOCAB;
    float mx = -1e30f;
    for (int j = threadIdx.x; j < VOCAB; j += 256) mx = fmaxf(mx, row[j]);
    mx = blockReduceMax(mx);
    float sum = 0.f;
    for (int j = threadIdx.x; j < VOCAB; j += 256) sum += expf(row[j] - mx);
    sum = blockReduceSum(sum);
    if (threadIdx.x == 0) {
        int tgt = labels[t + 1];
        if (tgt != -100) {
            float lp = row[tgt] - mx - logf(sum);
            atomicAdd(&g_loss[0], -lp);
            atomicAdd(&g_loss[1], 1.f);
        }
    }
}

__global__ void loss_final_kernel(float* __restrict__ out, int idx) {
    out[idx] = g_loss[0] / fmaxf(g_loss[1], 1.f);
}

// ---------------- driver ----------------
extern "C" void kernel_launch(void* const* d_in, const int* in_sizes, int n_in,
                              void* d_out, int out_size) {
    const int*   ids    = (const int*)  d_in[0];
    const int*   labels = (const int*)  d_in[1];
    const float* emb    = (const float*)d_in[2];
    const float* pos    = (const float*)d_in[3];
    const float* fnw    = (const float*)d_in[4];
    const float* nw     = (const float*)d_in[5];
    const float* inw    = (const float*)d_in[6];
    const float* cw     = (const float*)d_in[7];
    const float* cb     = (const float*)d_in[8];
    const float* xw     = (const float*)d_in[9];
    const float* dw     = (const float*)d_in[10];
    const float* db     = (const float*)d_in[11];
    const float* alog   = (const float*)d_in[12];
    const float* dp     = (const float*)d_in[13];
    const float* ow     = (const float*)d_in[14];
    float* out = (float*)d_out;

    float *ph, *pxz, *pu, *puT, *pxpart, *pbcT, *pdT;
    __half *pa16, *pwe16, *pwi16, *pwo16;
    cudaGetSymbolAddress((void**)&ph,     g_h);
    cudaGetSymbolAddress((void**)&pxz,    g_xz);
    cudaGetSymbolAddress((void**)&pu,     g_u);
    cudaGetSymbolAddress((void**)&puT,    g_uT);
    cudaGetSymbolAddress((void**)&pxpart, g_xpart);
    cudaGetSymbolAddress((void**)&pbcT,   g_bcT);
    cudaGetSymbolAddress((void**)&pdT,    g_deltaT);
    cudaGetSymbolAddress((void**)&pa16,   g_a16);
    cudaGetSymbolAddress((void**)&pwe16,  g_wemb16);
    cudaGetSymbolAddress((void**)&pwi16,  g_win16);
    cudaGetSymbolAddress((void**)&pwo16,  g_wout16);

    cudaFuncSetAttribute((const void*)gemm_hmma_kernel<0, 128, 64, 2>,
        cudaFuncAttributeMaxDynamicSharedMemorySize, HT_SMEM_128_64);
    cudaFuncSetAttribute((const void*)gemm_hmma_kernel<2, 64, 128, 1>,
        cudaFuncAttributeMaxDynamicSharedMemorySize, HT_SMEM_64_128);

    embed_kernel<<<(LSEQ * DMODEL + 255) / 256, 256>>>(ids, emb, pos);
    {
        int total = CVT_N1 + CVT_N2 + CVT_N3;
        cvt_all_kernel<<<(total / 4 + 255) / 256, 256>>>(
            emb, inw, ow, pwe16, pwi16, pwo16);
    }

    for (int l = 0; l < NLAYER; l++) {
        const float* nw_l  = nw   + (size_t)l * DMODEL;
        const float* cw_l  = cw   + (size_t)l * DINNER * DCONV;
        const float* cb_l  = cb   + (size_t)l * DINNER;
        const float* xw_l  = xw   + (size_t)l * XDIM * DINNER;
        const float* dw_l  = dw   + (size_t)l * DINNER * DTRANK;
        const float* db_l  = db   + (size_t)l * DINNER;
        const float* al_l  = alog + (size_t)l * DINNER * DSTATE;
        const float* dp_l  = dp   + (size_t)l * DINNER;
        const __half* wi_l = pwi16 + (size_t)l * 2 * DINNER * DMODEL;
        const __half* wo_l = pwo16 + (size_t)l * DMODEL * DINNER;

        // x = rmsnorm(h) -> fp16 (warp per token)
        rmsnorm_kernel<<<LSEQ / 8, 256>>>(ph, nw_l, pa16);
        // xz = x @ in_w^T  [2048 x 2048], K=512 (HMMA)
        gemm_hmma_kernel<0, 128, 64, 2>
            <<<dim3(2 * DINNER / 128, LSEQ / 128), 256, HT_SMEM_128_64>>>(
            DMODEL, pa16, DMODEL, wi_l, DMODEL, pxz, 2 * DINNER, nullptr);
        // u = silu(causal depthwise conv(xi) + b)  (u and u_T, both coalesced)
        conv_silu_kernel<<<dim3(DINNER / 64, LSEQ / 32), 256>>>(cw_l, cb_l);
        // xdbl partials = u @ xproj_w^T  [2048 x 64], K=1024, split-K x4 (fp32)
        gemm64_kernel<0, 0><<<dim3(1, LSEQ / 64, 4), 256>>>(
            DINNER / 4, pu, DINNER, xw_l, DINNER, pxpart, XDIM, LSEQ * XDIM, nullptr);
        // reduce bc partials -> bcT [32x2048]
        reduce4_kernel<<<(2 * DSTATE * LSEQ + 255) / 256, 256>>>();
        // delta_T = softplus((sum dt partials) @ dt_w^T + dt_b)^T  [1024 x 2048]
        gemm64_kernel<1, 1><<<dim3(DINNER / 64, LSEQ / 64), 256>>>(
            DTRANK, pxpart, XDIM, dw_l, DTRANK, pdT, LSEQ, 0, db_l);
        // selective scan + fused (y + u*Dp)*silu(z) -> fp16
        scan_kernel<<<DINNER / 8, 128>>>(pdT, puT, pbcT, al_l, pxz, dp_l, pa16);
        // h = h + yf @ out_w^T  [2048 x 512], K=1024 (HMMA)
        gemm_hmma_kernel<2, 64, 128, 1>
            <<<dim3(DMODEL / 64, LSEQ / 128), 256, HT_SMEM_64_128>>>(
            DINNER, pa16, DINNER, wo_l, DINNER, ph, DMODEL, ph);
    }

    // final norm + logits (HMMA)
    rmsnorm_kernel<<<LSEQ / 8, 256>>>(ph, fnw, pa16);
    gemm_hmma_kernel<0, 128, 64, 2>
        <<<dim3(VOCAB / 128, LSEQ / 128), 256, HT_SMEM_128_64>>>(
        DMODEL, pa16, DMODEL, pwe16, DMODEL, out, VOCAB, nullptr);

    // loss
    loss_init_kernel<<<1, 1>>>();
    loss_kernel<<<LSEQ - 1, 256>>>(labels, out);
    loss_final_kernel<<<1, 1>>>(out, out_size - 1);
}

// round 17
// speedup vs baseline: 1.3780x; 1.1307x over previous
#include <cuda_runtime.h>
#include <cuda_fp16.h>
#include <math.h>
#include <stdint.h>

#define LSEQ   2048
#define DMODEL 512
#define NLAYER 8
#define DSTATE 16
#define DCONV  4
#define DINNER 1024
#define DTRANK 32
#define VOCAB  4096
#define XDIM   64   // DT_RANK + 2*D_STATE
#define NCHUNK 8
#define CLEN   (LSEQ / NCHUNK)          // 256
#define NST    (DINNER * DSTATE)        // 16384

// ---------------- scratch (static device globals; no allocation) ----------------
__device__ float g_h[LSEQ * DMODEL];
__device__ float g_xz[LSEQ * 2 * DINNER];
__device__ float g_u[LSEQ * DINNER];
__device__ float g_uT[DINNER * LSEQ];
__device__ float g_xpart[4 * LSEQ * XDIM];
__device__ float g_bcT[2 * DSTATE * LSEQ];  // B rows [0..15], C rows [16..31], transposed
__device__ float g_deltaT[DINNER * LSEQ];
__device__ float g_hend[NCHUNK * NST];
__device__ float g_prod[NCHUNK * NST];
__device__ float g_h0[NCHUNK * NST];
__device__ float g_loss[2];

// fp16 buffers
__device__ __half g_a16[LSEQ * DINNER];
__device__ __half g_wemb16[VOCAB * DMODEL];
__device__ __half g_win16[NLAYER * 2 * DINNER * DMODEL];
__device__ __half g_wout16[NLAYER * DMODEL * DINNER];

// =============================== PTX helpers ===============================
__device__ __forceinline__ uint32_t smem_to_u32(const void* p) {
    uint32_t a;
    asm("{ .reg .u64 t; cvta.to.shared.u64 t, %1; cvt.u32.u64 %0, t; }"
        : "=r"(a) : "l"(p));
    return a;
}

#define CP_ASYNC_16(dst, src) \
    asm volatile("cp.async.cg.shared.global [%0], [%1], 16;" \
        :: "r"(dst), "l"(src) : "memory")
#define CP_ASYNC_COMMIT() asm volatile("cp.async.commit_group;" ::: "memory")
#define CP_ASYNC_WAIT0()  asm volatile("cp.async.wait_group 0;" ::: "memory")

__device__ __forceinline__ void ldmatrix_x4(uint32_t* r, uint32_t addr) {
    asm volatile("ldmatrix.sync.aligned.m8n8.x4.shared.b16 {%0,%1,%2,%3}, [%4];"
        : "=r"(r[0]), "=r"(r[1]), "=r"(r[2]), "=r"(r[3]) : "r"(addr));
}

__device__ __forceinline__ void mma16816(float* c, const uint32_t* a, const uint32_t* b) {
    asm volatile(
        "mma.sync.aligned.m16n8k16.row.col.f32.f16.f16.f32 "
        "{%0,%1,%2,%3}, {%4,%5,%6,%7}, {%8,%9}, {%0,%1,%2,%3};"
        : "+f"(c[0]), "+f"(c[1]), "+f"(c[2]), "+f"(c[3])
        : "r"(a[0]), "r"(a[1]), "r"(a[2]), "r"(a[3]), "r"(b[0]), "r"(b[1]));
}

// ======================= fp16 HMMA GEMM (r11 config — frozen) =======================
template <int ROWS, int CHUNK>
__device__ __forceinline__ void hmma_fill(
    uint32_t sdst, const __half* __restrict__ g, int ld, int row0, int k0, int tid) {
    constexpr int STRIDE = CHUNK + 8;
    constexpr int SEGS = CHUNK / 8;
    #pragma unroll
    for (int r = 0; r < ROWS * SEGS / 256; r++) {
        int idx = r * 256 + tid;
        int row = idx / SEGS, seg = idx % SEGS;
        uint32_t so = sdst + (uint32_t)(row * STRIDE + seg * 8) * 2;
        const void* gp = g + (size_t)(row0 + row) * ld + k0 + seg * 8;
        CP_ASYNC_16(so, gp);
    }
}

// EPI: 0 = store, 2 = += resid
template <int EPI, int BN, int CHUNK, int OCC>
__global__ void __launch_bounds__(256, OCC) gemm_hmma_kernel(
    int K,
    const __half* __restrict__ A, int lda,
    const __half* __restrict__ B, int ldb,
    float* __restrict__ C, int ldc,
    const float* __restrict__ resid) {
    extern __shared__ __half smem[];
    const uint32_t sbu = smem_to_u32(smem);
    const int tid = threadIdx.x;
    const int wid = tid >> 5, lane = tid & 31;
    const int bm0 = blockIdx.y * 128, bn0 = blockIdx.x * BN;

    constexpr int STRIDE = CHUNK + 8;
    constexpr int A_ELE = 128 * STRIDE;
    constexpr int B_ELE = BN * STRIDE;
    constexpr int BUF_ELE = A_ELE + B_ELE;
    constexpr int MT = (BN == 128) ? 4 : 2;

    const int wm = (BN == 128) ? (wid >> 2) * 64 : (wid >> 1) * 32;
    const int wn = (BN == 128) ? (wid & 3) * 32 : (wid & 1) * 32;

    float acc[MT][4][4];
    #pragma unroll
    for (int i = 0; i < MT; i++)
        #pragma unroll
        for (int j = 0; j < 4; j++)
            #pragma unroll
            for (int q = 0; q < 4; q++) acc[i][j][q] = 0.f;

    const int NC = K / CHUNK;

    hmma_fill<128, CHUNK>(sbu,            A, lda, bm0, 0, tid);
    hmma_fill<BN, CHUNK>(sbu + A_ELE * 2, B, ldb, bn0, 0, tid);
    CP_ASYNC_COMMIT();

    const int a_row = ((lane >> 3) & 1) * 8 + (lane & 7);
    const int a_col = ((lane >> 4) & 1) * 8;
    const int b_row = ((lane >> 4) & 1) * 8 + (lane & 7);
    const int b_col = ((lane >> 3) & 1) * 8;

    for (int ck = 0; ck < NC; ck++) {
        const int b = ck & 1;
        CP_ASYNC_WAIT0();
        __syncthreads();
        if (ck + 1 < NC) {
            uint32_t nb = sbu + (uint32_t)((b ^ 1) * BUF_ELE) * 2;
            const int k0 = (ck + 1) * CHUNK;
            hmma_fill<128, CHUNK>(nb,            A, lda, bm0, k0, tid);
            hmma_fill<BN, CHUNK>(nb + A_ELE * 2, B, ldb, bn0, k0, tid);
            CP_ASYNC_COMMIT();
        }

        const uint32_t sA = sbu + (uint32_t)(b * BUF_ELE) * 2;
        const uint32_t sB = sA + (uint32_t)A_ELE * 2;

        #pragma unroll
        for (int kk = 0; kk < CHUNK / 16; kk++) {
            const int kc = kk * 16;
            uint32_t ah[MT][4], bh[4][2];
            #pragma unroll
            for (int mt = 0; mt < MT; mt++) {
                uint32_t off = (uint32_t)((wm + mt * 16 + a_row) * STRIDE + kc + a_col) * 2;
                ldmatrix_x4(ah[mt], sA + off);
            }
            #pragma unroll
            for (int nt2 = 0; nt2 < 2; nt2++) {
                uint32_t off = (uint32_t)((wn + nt2 * 16 + b_row) * STRIDE + kc + b_col) * 2;
                uint32_t r[4];
                ldmatrix_x4(r, sB + off);
                bh[nt2 * 2][0] = r[0]; bh[nt2 * 2][1] = r[1];
                bh[nt2 * 2 + 1][0] = r[2]; bh[nt2 * 2 + 1][1] = r[3];
            }
            #pragma unroll
            for (int mt = 0; mt < MT; mt++)
                #pragma unroll
                for (int nt = 0; nt < 4; nt++)
                    mma16816(acc[mt][nt], ah[mt], bh[nt]);
        }
        __syncthreads();
    }

    const int er = lane >> 2, ec = (lane & 3) * 2;
    #pragma unroll
    for (int mt = 0; mt < MT; mt++) {
        #pragma unroll
        for (int nt = 0; nt < 4; nt++) {
            int row = bm0 + wm + mt * 16 + er;
            int col = bn0 + wn + nt * 8 + ec;
            float2 v0 = make_float2(acc[mt][nt][0], acc[mt][nt][1]);
            float2 v1 = make_float2(acc[mt][nt][2], acc[mt][nt][3]);
            if (EPI == 2) {
                const float2 r0 = *reinterpret_cast<const float2*>(
                    resid + (size_t)row * ldc + col);
                const float2 r1 = *reinterpret_cast<const float2*>(
                    resid + (size_t)(row + 8) * ldc + col);
                v0.x += r0.x; v0.y += r0.y;
                v1.x += r1.x; v1.y += r1.y;
            }
            *reinterpret_cast<float2*>(C + (size_t)row * ldc + col) = v0;
            *reinterpret_cast<float2*>(C + (size_t)(row + 8) * ldc + col) = v1;
        }
    }
}

#define HT_SMEM(BN, CHUNK) (2 * (128 + (BN)) * ((CHUNK) + 8) * 2)
#define HT_SMEM_128_64 HT_SMEM(128, 64)
#define HT_SMEM_64_128 HT_SMEM(64, 128)

// ---------------- fused fp32 -> fp16 conversion of all weights ----------------
#define CVT_N1 (VOCAB * DMODEL)
#define CVT_N2 (NLAYER * 2 * DINNER * DMODEL)
#define CVT_N3 (NLAYER * DMODEL * DINNER)
__global__ void cvt_all_kernel(const float* __restrict__ emb,
                               const float* __restrict__ inw,
                               const float* __restrict__ ow,
                               __half* __restrict__ we16,
                               __half* __restrict__ wi16,
                               __half* __restrict__ wo16) {
    int i = (blockIdx.x * blockDim.x + threadIdx.x) * 4;
    const float* src;
    __half* dst;
    if (i < CVT_N1) {
        src = emb + i; dst = we16 + i;
    } else if (i < CVT_N1 + CVT_N2) {
        src = inw + (i - CVT_N1); dst = wi16 + (i - CVT_N1);
    } else if (i < CVT_N1 + CVT_N2 + CVT_N3) {
        src = ow + (i - CVT_N1 - CVT_N2); dst = wo16 + (i - CVT_N1 - CVT_N2);
    } else {
        return;
    }
    float4 v = *reinterpret_cast<const float4*>(src);
    *reinterpret_cast<__half2*>(dst)     = __floats2half2_rn(v.x, v.y);
    *reinterpret_cast<__half2*>(dst + 2) = __floats2half2_rn(v.z, v.w);
}

// ---------------- block reductions (loss only) ----------------
__device__ __forceinline__ float blockReduceSum(float v) {
    __shared__ float sh[9];
    int lane = threadIdx.x & 31, w = threadIdx.x >> 5;
    #pragma unroll
    for (int o = 16; o; o >>= 1) v += __shfl_xor_sync(0xffffffffu, v, o);
    if (lane == 0) sh[w] = v;
    __syncthreads();
    if (threadIdx.x == 0) {
        float s = 0.f;
        int nw = (blockDim.x + 31) >> 5;
        for (int i = 0; i < nw; i++) s += sh[i];
        sh[8] = s;
    }
    __syncthreads();
    float r = sh[8];
    __syncthreads();
    return r;
}

__device__ __forceinline__ float blockReduceMax(float v) {
    __shared__ float sh[9];
    int lane = threadIdx.x & 31, w = threadIdx.x >> 5;
    #pragma unroll
    for (int o = 16; o; o >>= 1) v = fmaxf(v, __shfl_xor_sync(0xffffffffu, v, o));
    if (lane == 0) sh[w] = v;
    __syncthreads();
    if (threadIdx.x == 0) {
        float s = -1e30f;
        int nw = (blockDim.x + 31) >> 5;
        for (int i = 0; i < nw; i++) s = fmaxf(s, sh[i]);
        sh[8] = s;
    }
    __syncthreads();
    float r = sh[8];
    __syncthreads();
    return r;
}

// ---------------- embedding ----------------
__global__ void embed_kernel(const int* __restrict__ ids,
                             const float* __restrict__ emb,
                             const float* __restrict__ pos) {
    int i = blockIdx.x * blockDim.x + threadIdx.x;
    if (i >= LSEQ * DMODEL) return;
    int t = i / DMODEL;
    int d = i - t * DMODEL;
    g_h[i] = emb[(size_t)ids[t] * DMODEL + d] + pos[i];
}

// ---------------- rmsnorm -> fp16, warp per token ----------------
__global__ void rmsnorm_kernel(const float* __restrict__ src,
                               const float* __restrict__ w,
                               __half* __restrict__ dst) {
    int warp = threadIdx.x >> 5, lane = threadIdx.x & 31;
    int t = blockIdx.x * 8 + warp;
    const float* r = src + (size_t)t * DMODEL;
    float4 v[4];
    float ss = 0.f;
    #pragma unroll
    for (int q = 0; q < 4; q++) {
        v[q] = *reinterpret_cast<const float4*>(r + (q * 32 + lane) * 4);
        ss += v[q].x * v[q].x + v[q].y * v[q].y + v[q].z * v[q].z + v[q].w * v[q].w;
    }
    #pragma unroll
    for (int o = 16; o; o >>= 1) ss += __shfl_xor_sync(0xffffffffu, ss, o);
    float sc = rsqrtf(ss * (1.0f / DMODEL) + 1e-6f);
    __half* dp = dst + (size_t)t * DMODEL;
    #pragma unroll
    for (int q = 0; q < 4; q++) {
        int idx = (q * 32 + lane) * 4;
        float4 w4 = *reinterpret_cast<const float4*>(w + idx);
        __half2 h0 = __floats2half2_rn(v[q].x * sc * w4.x, v[q].y * sc * w4.y);
        __half2 h1 = __floats2half2_rn(v[q].z * sc * w4.z, v[q].w * sc * w4.w);
        *reinterpret_cast<__half2*>(dp + idx)     = h0;
        *reinterpret_cast<__half2*>(dp + idx + 2) = h1;
    }
}

// =================================================================================
// fp32 GEMM 64x64x16 (small xproj/dt), double-buffered, 256 threads, 4x4/thread
// split-K via blockIdx.z. EPI: 0 = store, 1 = softplus(v+bias[col]) transposed
// SUMA: A = sum of 4 split-K partials at stride LSEQ*XDIM
// =================================================================================
template <int EPI, int SUMA>
__global__ void __launch_bounds__(256) gemm64_kernel(
    int Kloc,
    const float* __restrict__ A, int lda,
    const float* __restrict__ B, int ldb,
    float* __restrict__ C, int ldc, int partStride,
    const float* __restrict__ bias) {
    __shared__ float As[2][16][68];
    __shared__ float Bs[2][16][68];
    const int tid = threadIdx.x;
    const int bm0 = blockIdx.y * 64, bn0 = blockIdx.x * 64;
    const int kbase = blockIdx.z * Kloc;
    C += (size_t)blockIdx.z * partStride;

    const int lrow = tid >> 2;
    const int kq0  = (tid & 3) << 2;
    const float* Ap = A + (size_t)(bm0 + lrow) * lda + kbase + kq0;
    const float* Bp = B + (size_t)(bn0 + lrow) * ldb + kbase + kq0;
    const int PS = LSEQ * XDIM;

    const int ty = tid >> 4, tx = tid & 15;

    float acc[4][4];
    #pragma unroll
    for (int i = 0; i < 4; i++)
        #pragma unroll
        for (int j = 0; j < 4; j++) acc[i][j] = 0.f;

    auto loadA = [&](int off) -> float4 {
        float4 a = *reinterpret_cast<const float4*>(Ap + off);
        if (SUMA) {
            float4 p1 = *reinterpret_cast<const float4*>(Ap + off + PS);
            float4 p2 = *reinterpret_cast<const float4*>(Ap + off + 2 * PS);
            float4 p3 = *reinterpret_cast<const float4*>(Ap + off + 3 * PS);
            a.x = a.x + p1.x + p2.x + p3.x;
            a.y = a.y + p1.y + p2.y + p3.y;
            a.z = a.z + p1.z + p2.z + p3.z;
            a.w = a.w + p1.w + p2.w + p3.w;
        }
        return a;
    };

    float4 av = loadA(0);
    float4 bv = *reinterpret_cast<const float4*>(Bp);
    As[0][kq0 + 0][lrow] = av.x; As[0][kq0 + 1][lrow] = av.y;
    As[0][kq0 + 2][lrow] = av.z; As[0][kq0 + 3][lrow] = av.w;
    Bs[0][kq0 + 0][lrow] = bv.x; Bs[0][kq0 + 1][lrow] = bv.y;
    Bs[0][kq0 + 2][lrow] = bv.z; Bs[0][kq0 + 3][lrow] = bv.w;
    __syncthreads();

    const int KT = Kloc >> 4;
    for (int kt = 0; kt < KT; kt++) {
        const int cur = kt & 1, nxt = cur ^ 1;
        if (kt + 1 < KT) {
            int off = (kt + 1) << 4;
            av = loadA(off);
            bv = *reinterpret_cast<const float4*>(Bp + off);
        }
        #pragma unroll
        for (int kk = 0; kk < 16; kk++) {
            float4 a4 = *reinterpret_cast<const float4*>(&As[cur][kk][ty * 4]);
            float4 b4 = *reinterpret_cast<const float4*>(&Bs[cur][kk][tx * 4]);
            float a[4] = {a4.x, a4.y, a4.z, a4.w};
            float b[4] = {b4.x, b4.y, b4.z, b4.w};
            #pragma unroll
            for (int i = 0; i < 4; i++)
                #pragma unroll
                for (int j = 0; j < 4; j++)
                    acc[i][j] = fmaf(a[i], b[j], acc[i][j]);
        }
        if (kt + 1 < KT) {
            As[nxt][kq0 + 0][lrow] = av.x; As[nxt][kq0 + 1][lrow] = av.y;
            As[nxt][kq0 + 2][lrow] = av.z; As[nxt][kq0 + 3][lrow] = av.w;
            Bs[nxt][kq0 + 0][lrow] = bv.x; Bs[nxt][kq0 + 1][lrow] = bv.y;
            Bs[nxt][kq0 + 2][lrow] = bv.z; Bs[nxt][kq0 + 3][lrow] = bv.w;
            __syncthreads();
        }
    }

    if (EPI == 1) {
        float4 bias4 = *reinterpret_cast<const float4*>(&bias[bn0 + tx * 4]);
        float bb[4] = {bias4.x, bias4.y, bias4.z, bias4.w};
        #pragma unroll
        for (int i = 0; i < 4; i++)
            #pragma unroll
            for (int j = 0; j < 4; j++) {
                float v = acc[i][j] + bb[j];
                acc[i][j] = (v > 20.f) ? v : log1pf(expf(v));
            }
        int row0 = bm0 + ty * 4;
        #pragma unroll
        for (int j = 0; j < 4; j++) {
            int col = bn0 + tx * 4 + j;
            float4 v = make_float4(acc[0][j], acc[1][j], acc[2][j], acc[3][j]);
            *reinterpret_cast<float4*>(C + (size_t)col * ldc + row0) = v;
        }
    } else {
        #pragma unroll
        for (int i = 0; i < 4; i++) {
            int row = bm0 + ty * 4 + i;
            float* cp = C + (size_t)row * ldc + bn0 + tx * 4;
            *reinterpret_cast<float4*>(cp) =
                make_float4(acc[i][0], acc[i][1], acc[i][2], acc[i][3]);
        }
    }
}

// ---------------- reduce the 4 split-K partials: bcT only ----------------
__global__ void reduce4_kernel() {
    int j = blockIdx.x * blockDim.x + threadIdx.x;
    const int NB = 2 * DSTATE * LSEQ;
    const int PS = LSEQ * XDIM;
    if (j >= NB) return;
    int s2 = j >> 11, t = j & (LSEQ - 1);
    int b = t * XDIM + DTRANK + s2;
    g_bcT[j] = g_xpart[b] + g_xpart[b + PS] + g_xpart[b + 2 * PS] + g_xpart[b + 3 * PS];
}

// ---------------- depthwise causal conv (width 4) + bias + silu ----------------
__global__ void conv_silu_kernel(const float* __restrict__ cw,
                                 const float* __restrict__ cb) {
    __shared__ float su[64][33];
    const int c0 = blockIdx.x * 64;
    const int t0 = blockIdx.y * 32;
    const int tid = threadIdx.x;
    #pragma unroll
    for (int it = 0; it < 8; it++) {
        int idx = it * 256 + tid;
        int cl = idx & 63, tl = idx >> 6;
        int c = c0 + cl, t = t0 + tl;
        float v = cb[c];
        #pragma unroll
        for (int k = 0; k < DCONV; k++) {
            int tt = t - (DCONV - 1) + k;
            if (tt >= 0)
                v = fmaf(g_xz[(size_t)tt * (2 * DINNER) + c], cw[c * DCONV + k], v);
        }
        float s = v / (1.f + expf(-v));
        g_u[(size_t)t * DINNER + c] = s;
        su[cl][tl] = s;
    }
    __syncthreads();
    #pragma unroll
    for (int it = 0; it < 8; it++) {
        int cl = it * 8 + (tid >> 5);
        int tl = tid & 31;
        g_uT[(size_t)(c0 + cl) * LSEQ + (t0 + tl)] = su[cl][tl];
    }
}

// ---------------- chunked selective scan: pass 1 (recurrence + prod only) ----------------
__global__ void scan_pass1_kernel(const float* __restrict__ deltaT,
                                  const float* __restrict__ uT,
                                  const float* __restrict__ bcT,
                                  const float* __restrict__ A_log) {
    int warp = threadIdx.x >> 5;
    int lane = threadIdx.x & 31;
    int half = lane >> 4;
    int s    = lane & 15;
    int ch   = blockIdx.x * 8 + warp * 2 + half;
    int chunk = blockIdx.y;
    int tb = chunk * CLEN;

    float A2 = -__expf(A_log[ch * DSTATE + s]) * 1.44269504088896f;
    float h = 0.f, prod = 1.f;
    const float* dT  = deltaT + (size_t)ch * LSEQ + tb;
    const float* uTp = uT + (size_t)ch * LSEQ + tb;
    const float* bT  = bcT + (size_t)s * LSEQ + tb;

    for (int t0 = 0; t0 < CLEN; t0 += 16) {
        float dv[16], uv[16], bv[16];
        #pragma unroll
        for (int q = 0; q < 4; q++) {
            float4 d4 = *reinterpret_cast<const float4*>(dT + t0 + q * 4);
            float4 u4 = *reinterpret_cast<const float4*>(uTp + t0 + q * 4);
            float4 b4 = *reinterpret_cast<const float4*>(bT + t0 + q * 4);
            dv[q*4+0]=d4.x; dv[q*4+1]=d4.y; dv[q*4+2]=d4.z; dv[q*4+3]=d4.w;
            uv[q*4+0]=u4.x; uv[q*4+1]=u4.y; uv[q*4+2]=u4.z; uv[q*4+3]=u4.w;
            bv[q*4+0]=b4.x; bv[q*4+1]=b4.y; bv[q*4+2]=b4.z; bv[q*4+3]=b4.w;
        }
        #pragma unroll
        for (int j = 0; j < 16; j++) {
            float dA  = exp2f(dv[j] * A2);
            prod *= dA;
            h = fmaf(dA, h, dv[j] * uv[j] * bv[j]);
        }
    }
    int i = ch * DSTATE + s;
    g_hend[chunk * NST + i] = h;
    g_prod[chunk * NST + i] = prod;
}

// ---------------- chunked scan: carry chain across chunks ----------------
__global__ void scan_carry_kernel() {
    int i = blockIdx.x * blockDim.x + threadIdx.x;
    if (i >= NST) return;
    float h = 0.f;
    #pragma unroll
    for (int c = 0; c < NCHUNK; c++) {
        g_h0[c * NST + i] = h;
        h = g_prod[c * NST + i] * h + g_hend[c * NST + i];
    }
}

// ---------------- chunked scan: pass 2 (full, from correct h0) ----------------
__global__ void scan_pass2_kernel(const float* __restrict__ deltaT,
                                  const float* __restrict__ uT,
                                  const float* __restrict__ bcT,
                                  const float* __restrict__ A_log,
                                  const float* __restrict__ xz,
                                  const float* __restrict__ Dp,
                                  __half* __restrict__ yout) {
    int warp = threadIdx.x >> 5;
    int lane = threadIdx.x & 31;
    int half = lane >> 4;
    int s    = lane & 15;
    int ch   = blockIdx.x * 8 + warp * 2 + half;
    int chunk = blockIdx.y;
    int tb = chunk * CLEN;

    float A2 = -__expf(A_log[ch * DSTATE + s]) * 1.44269504088896f;
    float dpv = Dp[ch];
    float h = g_h0[chunk * NST + ch * DSTATE + s];
    const float* dT  = deltaT + (size_t)ch * LSEQ + tb;
    const float* uTp = uT + (size_t)ch * LSEQ + tb;
    const float* bT  = bcT + (size_t)s * LSEQ + tb;
    const float* cT  = bcT + (size_t)(DSTATE + s) * LSEQ + tb;

    const bool h8 = (s & 8), h4 = (s & 4), h2 = (s & 2), h1 = (s & 1);

    for (int t0 = 0; t0 < CLEN; t0 += 16) {
        float dv[16], uv[16], bv[16], cv[16];
        #pragma unroll
        for (int q = 0; q < 4; q++) {
            float4 d4 = *reinterpret_cast<const float4*>(dT + t0 + q * 4);
            float4 u4 = *reinterpret_cast<const float4*>(uTp + t0 + q * 4);
            float4 b4 = *reinterpret_cast<const float4*>(bT + t0 + q * 4);
            float4 c4 = *reinterpret_cast<const float4*>(cT + t0 + q * 4);
            dv[q*4+0]=d4.x; dv[q*4+1]=d4.y; dv[q*4+2]=d4.z; dv[q*4+3]=d4.w;
            uv[q*4+0]=u4.x; uv[q*4+1]=u4.y; uv[q*4+2]=u4.z; uv[q*4+3]=u4.w;
            bv[q*4+0]=b4.x; bv[q*4+1]=b4.y; bv[q*4+2]=b4.z; bv[q*4+3]=b4.w;
            cv[q*4+0]=c4.x; cv[q*4+1]=c4.y; cv[q*4+2]=c4.z; cv[q*4+3]=c4.w;
        }
        float p[16];
        #pragma unroll
        for (int j = 0; j < 16; j++) {
            float dA  = exp2f(dv[j] * A2);
            float dbu = dv[j] * uv[j] * bv[j];
            h = fmaf(dA, h, dbu);
            p[j] = h * cv[j];
        }
        // transpose-reduce across the 16 state lanes
        float q8[8];
        #pragma unroll
        for (int j = 0; j < 8; j++) {
            float keep = h8 ? p[j + 8] : p[j];
            float send = h8 ? p[j] : p[j + 8];
            q8[j] = keep + __shfl_xor_sync(0xffffffffu, send, 8);
        }
        float q4[4];
        #pragma unroll
        for (int j = 0; j < 4; j++) {
            float keep = h4 ? q8[j + 4] : q8[j];
            float send = h4 ? q8[j] : q8[j + 4];
            q4[j] = keep + __shfl_xor_sync(0xffffffffu, send, 4);
        }
        float q2[2];
        #pragma unroll
        for (int j = 0; j < 2; j++) {
            float keep = h2 ? q4[j + 2] : q4[j];
            float send = h2 ? q4[j] : q4[j + 2];
            q2[j] = keep + __shfl_xor_sync(0xffffffffu, send, 2);
        }
        float keep1 = h1 ? q2[1] : q2[0];
        float send1 = h1 ? q2[0] : q2[1];
        float out = keep1 + __shfl_xor_sync(0xffffffffu, send1, 1);

        float uo = 0.f;
        #pragma unroll
        for (int j = 0; j < 16; j++)
            if (s == j) uo = uv[j];

        int t = tb + t0 + s;
        float zz = xz[(size_t)t * (2 * DINNER) + DINNER + ch];
        float sz = zz / (1.f + expf(-zz));
        yout[(size_t)t * DINNER + ch] = __float2half((out + uo * dpv) * sz);
    }
}

// ---------------- cross-entropy loss over logits ----------------
__global__ void loss_init_kernel() { g_loss[0] = 0.f; g_loss[1] = 0.f; }

__global__ void loss_kernel(const int* __restrict__ labels,
                            const float* __restrict__ logits) {
    int t = blockIdx.x;
    const float* row = logits + (size_t)t * VOCAB;
    float mx = -1e30f;
    for (int j = threadIdx.x; j < VOCAB; j += 256) mx = fmaxf(mx, row[j]);
    mx = blockReduceMax(mx);
    float sum = 0.f;
    for (int j = threadIdx.x; j < VOCAB; j += 256) sum += expf(row[j] - mx);
    sum = blockReduceSum(sum);
    if (threadIdx.x == 0) {
        int tgt = labels[t + 1];
        if (tgt != -100) {
            float lp = row[tgt] - mx - logf(sum);
            atomicAdd(&g_loss[0], -lp);
            atomicAdd(&g_loss[1], 1.f);
        }
    }
}

__global__ void loss_final_kernel(float* __restrict__ out, int idx) {
    out[idx] = g_loss[0] / fmaxf(g_loss[1], 1.f);
}

// ---------------- driver ----------------
extern "C" void kernel_launch(void* const* d_in, const int* in_sizes, int n_in,
                              void* d_out, int out_size) {
    const int*   ids    = (const int*)  d_in[0];
    const int*   labels = (const int*)  d_in[1];
    const float* emb    = (const float*)d_in[2];
    const float* pos    = (const float*)d_in[3];
    const float* fnw    = (const float*)d_in[4];
    const float* nw     = (const float*)d_in[5];
    const float* inw    = (const float*)d_in[6];
    const float* cw     = (const float*)d_in[7];
    const float* cb     = (const float*)d_in[8];
    const float* xw     = (const float*)d_in[9];
    const float* dw     = (const float*)d_in[10];
    const float* db     = (const float*)d_in[11];
    const float* alog   = (const float*)d_in[12];
    const float* dp     = (const float*)d_in[13];
    const float* ow     = (const float*)d_in[14];
    float* out = (float*)d_out;

    float *ph, *pxz, *pu, *puT, *pxpart, *pbcT, *pdT;
    __half *pa16, *pwe16, *pwi16, *pwo16;
    cudaGetSymbolAddress((void**)&ph,     g_h);
    cudaGetSymbolAddress((void**)&pxz,    g_xz);
    cudaGetSymbolAddress((void**)&pu,     g_u);
    cudaGetSymbolAddress((void**)&puT,    g_uT);
    cudaGetSymbolAddress((void**)&pxpart, g_xpart);
    cudaGetSymbolAddress((void**)&pbcT,   g_bcT);
    cudaGetSymbolAddress((void**)&pdT,    g_deltaT);
    cudaGetSymbolAddress((void**)&pa16,   g_a16);
    cudaGetSymbolAddress((void**)&pwe16,  g_wemb16);
    cudaGetSymbolAddress((void**)&pwi16,  g_win16);
    cudaGetSymbolAddress((void**)&pwo16,  g_wout16);

    cudaFuncSetAttribute((const void*)gemm_hmma_kernel<0, 128, 64, 2>,
        cudaFuncAttributeMaxDynamicSharedMemorySize, HT_SMEM_128_64);
    cudaFuncSetAttribute((const void*)gemm_hmma_kernel<2, 64, 128, 1>,
        cudaFuncAttributeMaxDynamicSharedMemorySize, HT_SMEM_64_128);

    embed_kernel<<<(LSEQ * DMODEL + 255) / 256, 256>>>(ids, emb, pos);
    {
        int total = CVT_N1 + CVT_N2 + CVT_N3;
        cvt_all_kernel<<<(total / 4 + 255) / 256, 256>>>(
            emb, inw, ow, pwe16, pwi16, pwo16);
    }

    for (int l = 0; l < NLAYER; l++) {
        const float* nw_l  = nw   + (size_t)l * DMODEL;
        const float* cw_l  = cw   + (size_t)l * DINNER * DCONV;
        const float* cb_l  = cb   + (size_t)l * DINNER;
        const float* xw_l  = xw   + (size_t)l * XDIM * DINNER;
        const float* dw_l  = dw   + (size_t)l * DINNER * DTRANK;
        const float* db_l  = db   + (size_t)l * DINNER;
        const float* al_l  = alog + (size_t)l * DINNER * DSTATE;
        const float* dp_l  = dp   + (size_t)l * DINNER;
        const __half* wi_l = pwi16 + (size_t)l * 2 * DINNER * DMODEL;
        const __half* wo_l = pwo16 + (size_t)l * DMODEL * DINNER;

        // x = rmsnorm(h) -> fp16
        rmsnorm_kernel<<<LSEQ / 8, 256>>>(ph, nw_l, pa16);
        // xz = x @ in_w^T  [2048 x 2048], K=512 (HMMA)
        gemm_hmma_kernel<0, 128, 64, 2>
            <<<dim3(2 * DINNER / 128, LSEQ / 128), 256, HT_SMEM_128_64>>>(
            DMODEL, pa16, DMODEL, wi_l, DMODEL, pxz, 2 * DINNER, nullptr);
        // u = silu(causal depthwise conv(xi) + b)
        conv_silu_kernel<<<dim3(DINNER / 64, LSEQ / 32), 256>>>(cw_l, cb_l);
        // xdbl partials = u @ xproj_w^T  [2048 x 64], K=1024, split-K x4 (fp32)
        gemm64_kernel<0, 0><<<dim3(1, LSEQ / 64, 4), 256>>>(
            DINNER / 4, pu, DINNER, xw_l, DINNER, pxpart, XDIM, LSEQ * XDIM, nullptr);
        // reduce bc partials -> bcT
        reduce4_kernel<<<(2 * DSTATE * LSEQ + 255) / 256, 256>>>();
        // delta_T = softplus((sum dt partials) @ dt_w^T + dt_b)^T
        gemm64_kernel<1, 1><<<dim3(DINNER / 64, LSEQ / 64), 256>>>(
            DTRANK, pxpart, XDIM, dw_l, DTRANK, pdT, LSEQ, 0, db_l);
        // chunked scan: pass1 (local recurrences) -> carry -> pass2 (full + y)
        scan_pass1_kernel<<<dim3(DINNER / 8, NCHUNK), 128>>>(pdT, puT, pbcT, al_l);
        scan_carry_kernel<<<NST / 256, 256>>>();
        scan_pass2_kernel<<<dim3(DINNER / 8, NCHUNK), 128>>>(
            pdT, puT, pbcT, al_l, pxz, dp_l, pa16);
        // h = h + yf @ out_w^T  [2048 x 512], K=1024 (HMMA)
        gemm_hmma_kernel<2, 64, 128, 1>
            <<<dim3(DMODEL / 64, LSEQ / 128), 256, HT_SMEM_64_128>>>(
            DINNER, pa16, DINNER, wo_l, DINNER, ph, DMODEL, ph);
    }

    // final norm + logits (HMMA)
    rmsnorm_kernel<<<LSEQ / 8, 256>>>(ph, fnw, pa16);
    gemm_hmma_kernel<0, 128, 64, 2>
        <<<dim3(VOCAB / 128, LSEQ / 128), 256, HT_SMEM_128_64>>>(
        DMODEL, pa16, DMODEL, pwe16, DMODEL, out, VOCAB, nullptr);

    // loss
    loss_init_kernel<<<1, 1>>>();
    loss_kernel<<<LSEQ - 1, 256>>>(labels, out);
    loss_final_kernel<<<1, 1>>>(out, out_size - 1);
}